// round 3
// baseline (speedup 1.0000x reference)
#include <cuda_runtime.h>
#include <cuda_fp16.h>
#include <cstdint>

// Problem constants
#define N_ATOMS 100000
#define N_EDGES 1000000
#define HID 64
#define OUTD 128

#define SCAN_T 512
#define SCAN_ITEMS (N_ATOMS + 1)
#define SCAN_NB ((SCAN_ITEMS + SCAN_T - 1) / SCAN_T)

// Scratch (device globals: allocation-free rule)
__device__ float  g_x[N_ATOMS * HID];      // node features
__device__ float  g_lin[N_ATOMS * HID];    // x @ W_lin + b_lin, fp32 (self term)
__device__ __half g_linh[N_ATOMS * HID];   // same, fp16 (edge messages)
__device__ __half g_gtop[N_ATOMS * HID];   // x @ Wg_top + b_gate (gate pre-act)
__device__ __half g_gbot[N_ATOMS * HID];   // x @ Wg_bot
__device__ float  g_pooled[HID];

// Edge CSR (built per launch by counting sort)
__device__ int g_cnt[SCAN_ITEMS];
__device__ int g_off[SCAN_ITEMS];
__device__ int g_cur[N_ATOMS];
__device__ int g_part[SCAN_NB];
__device__ int g_scol[N_EDGES];

// ---------------------------------------------------------------------------
// 1. Embedding lookup + zero counters/pooled
// ---------------------------------------------------------------------------
__global__ void __launch_bounds__(256) embed_kernel(const int* __restrict__ an,
                                                    const float* __restrict__ emb) {
    int i = blockIdx.x * 256 + threadIdx.x;
    if (i < N_ATOMS * HID) {
        int v = i >> 6;
        g_x[i] = emb[an[v] * HID + (i & 63)];
    }
    if (i < SCAN_ITEMS) g_cnt[i] = 0;
    if (i < HID) g_pooled[i] = 0.0f;
}

// ---------------------------------------------------------------------------
// 2. Counting sort of edges by row  (hist -> scan -> scatter)
// ---------------------------------------------------------------------------
__global__ void __launch_bounds__(256) hist_kernel(const int* __restrict__ ei) {
    int e = blockIdx.x * 256 + threadIdx.x;
    if (e < N_EDGES) atomicAdd(&g_cnt[ei[e]], 1);
}

__global__ void __launch_bounds__(SCAN_T) scan_a_kernel() {
    __shared__ int s[SCAN_T];
    int t = threadIdx.x;
    int i = blockIdx.x * SCAN_T + t;
    s[t] = (i < SCAN_ITEMS) ? g_cnt[i] : 0;
    __syncthreads();
    for (int d = SCAN_T / 2; d > 0; d >>= 1) {
        if (t < d) s[t] += s[t + d];
        __syncthreads();
    }
    if (t == 0) g_part[blockIdx.x] = s[0];
}

// parallel exclusive scan over SCAN_NB (=196) partials, single block
__global__ void __launch_bounds__(256) scan_b_kernel() {
    __shared__ int s[256];
    int t = threadIdx.x;
    int v = (t < SCAN_NB) ? g_part[t] : 0;
    s[t] = v;
    __syncthreads();
    for (int d = 1; d < 256; d <<= 1) {
        int a = (t >= d) ? s[t - d] : 0;
        __syncthreads();
        s[t] += a;
        __syncthreads();
    }
    if (t < SCAN_NB) g_part[t] = s[t] - v;  // exclusive
}

__global__ void __launch_bounds__(SCAN_T) scan_c_kernel() {
    __shared__ int s[SCAN_T];
    int t = threadIdx.x;
    int i = blockIdx.x * SCAN_T + t;
    int v = (i < SCAN_ITEMS) ? g_cnt[i] : 0;
    s[t] = v;
    __syncthreads();
    for (int d = 1; d < SCAN_T; d <<= 1) {
        int a = (t >= d) ? s[t - d] : 0;
        __syncthreads();
        s[t] += a;
        __syncthreads();
    }
    int off = g_part[blockIdx.x] + s[t] - v;  // exclusive
    if (i < SCAN_ITEMS) g_off[i] = off;
    if (i < N_ATOMS)    g_cur[i] = off;
}

__global__ void __launch_bounds__(256) scatter_kernel(const int* __restrict__ ei) {
    int e = blockIdx.x * 256 + threadIdx.x;
    if (e < N_EDGES) {
        int r = ei[e];
        int c = ei[N_EDGES + e];
        int p = atomicAdd(&g_cur[r], 1);
        g_scol[p] = c;
    }
}

// ---------------------------------------------------------------------------
// 3. Per-node projection: [64 nodes/block] x (64 -> 192) GEMM
// ---------------------------------------------------------------------------
#define XS_STRIDE 68
#define PROJ_SMEM ((64 * XS_STRIDE + 64 * 192) * 4)

__global__ void __launch_bounds__(256) proj_kernel(const float* __restrict__ Wg,
                                                   const float* __restrict__ bg,
                                                   const float* __restrict__ Wl,
                                                   const float* __restrict__ bl) {
    extern __shared__ float sm[];
    float* xsT = sm;                    // [64][XS_STRIDE]
    float* ws  = sm + 64 * XS_STRIDE;   // [64][192]

    const int tid = threadIdx.x;
    const int node0 = blockIdx.x * 64;

    for (int i = tid; i < 64 * 64; i += 256) {
        int k = i & 63, n = i >> 6;
        int node = node0 + n;
        xsT[k * XS_STRIDE + n] = (node < N_ATOMS) ? g_x[node * HID + k] : 0.0f;
    }
    for (int i = tid; i < 64 * 192; i += 256) {
        int k = i / 192, c = i - k * 192;
        float w;
        if (c < 64)        w = Wg[k * 64 + c];
        else if (c < 128)  w = Wg[(64 + k) * 64 + (c - 64)];
        else               w = Wl[k * 64 + (c - 128)];
        ws[i] = w;
    }
    __syncthreads();

    const int ng = tid & 7;
    const int cg = tid >> 3;
    const int nb = ng * 8;
    const int cb = cg * 6;

    float acc[8][6];
    #pragma unroll
    for (int n = 0; n < 8; n++)
        #pragma unroll
        for (int j = 0; j < 6; j++) acc[n][j] = 0.0f;

    #pragma unroll 8
    for (int k = 0; k < 64; k++) {
        const float* xr = &xsT[k * XS_STRIDE + nb];
        float4 a0 = *reinterpret_cast<const float4*>(xr);
        float4 a1 = *reinterpret_cast<const float4*>(xr + 4);
        float a[8] = {a0.x, a0.y, a0.z, a0.w, a1.x, a1.y, a1.z, a1.w};
        float b[6];
        #pragma unroll
        for (int j = 0; j < 6; j++) b[j] = ws[k * 192 + cb + j];
        #pragma unroll
        for (int n = 0; n < 8; n++)
            #pragma unroll
            for (int j = 0; j < 6; j++) acc[n][j] += a[n] * b[j];
    }

    for (int n = 0; n < 8; n++) {
        int node = node0 + nb + n;
        if (node >= N_ATOMS) break;
        #pragma unroll
        for (int j = 0; j < 6; j++) {
            int c = cb + j;
            if (c < 64) {
                g_gtop[node * HID + c] = __float2half(acc[n][j] + bg[c]);
            } else if (c < 128) {
                g_gbot[node * HID + (c - 64)] = __float2half(acc[n][j]);
            } else {
                float lv = acc[n][j] + bl[c - 128];
                g_lin[node * HID + (c - 128)] = lv;
                g_linh[node * HID + (c - 128)] = __float2half(lv);
            }
        }
    }
}

// ---------------------------------------------------------------------------
// 4. Gather-aggregate + fused node update.
//    One warp per node; lane handles 2 channels as half2.
//    x[v] = relu( lin[v] + sum_{c in N(v)} sigmoid(gtop[v]+gbot[c]) * linh[c] )
//    Inner loop batches 8 edges: 16 loads in flight before any math.
// ---------------------------------------------------------------------------
__global__ void __launch_bounds__(256) gather_kernel() {
    int w = (blockIdx.x * 256 + threadIdx.x) >> 5;
    int l = threadIdx.x & 31;
    if (w >= N_ATOMS) return;

    int beg = __ldg(&g_off[w]);
    int end = __ldg(&g_off[w + 1]);

    const __half2* gt2 = reinterpret_cast<const __half2*>(g_gtop);
    const __half2* gb2 = reinterpret_cast<const __half2*>(g_gbot);
    const __half2* lh2 = reinterpret_cast<const __half2*>(g_linh);

    float2 gtf = __half22float2(gt2[(size_t)w * 32 + l]);
    float2 acc = *reinterpret_cast<const float2*>(g_lin + (size_t)w * HID + 2 * l);

    for (int base = beg; base < end; base += 32) {
        int rem = end - base;
        int myc = (l < rem) ? g_scol[base + l] : 0;
        int m = min(32, rem);
        for (int j0 = 0; j0 < m; j0 += 8) {
            int jm = m - j0;           // >=1
            __half2 gb[8], lh[8];
            int cc[8];
            #pragma unroll
            for (int j = 0; j < 8; j++)
                cc[j] = __shfl_sync(0xffffffffu, myc, j0 + j);
            #pragma unroll
            for (int j = 0; j < 8; j++) {
                if (j < jm) {
                    gb[j] = __ldg(&gb2[(size_t)cc[j] * 32 + l]);
                    lh[j] = __ldg(&lh2[(size_t)cc[j] * 32 + l]);
                }
            }
            #pragma unroll
            for (int j = 0; j < 8; j++) {
                if (j < jm) {
                    float2 gbf = __half22float2(gb[j]);
                    float2 lhf = __half22float2(lh[j]);
                    float t0, t1;
                    asm("tanh.approx.f32 %0, %1;" : "=f"(t0) : "f"(0.5f * (gtf.x + gbf.x)));
                    asm("tanh.approx.f32 %0, %1;" : "=f"(t1) : "f"(0.5f * (gtf.y + gbf.y)));
                    acc.x += (0.5f * t0 + 0.5f) * lhf.x;
                    acc.y += (0.5f * t1 + 0.5f) * lhf.y;
                }
            }
        }
    }

    float2 xo;
    xo.x = fmaxf(acc.x, 0.0f);
    xo.y = fmaxf(acc.y, 0.0f);
    *reinterpret_cast<float2*>(g_x + (size_t)w * HID + 2 * l) = xo;
}

// ---------------------------------------------------------------------------
// 5. Mean pool (sum; mean applied in head)
// ---------------------------------------------------------------------------
__global__ void __launch_bounds__(256) pool_kernel() {
    int t = threadIdx.x;
    int col = t & 63;
    int grp = t >> 6;
    float acc = 0.0f;
    for (int node = blockIdx.x * 4 + grp; node < N_ATOMS; node += gridDim.x * 4)
        acc += g_x[node * HID + col];
    __shared__ float s[256];
    s[t] = acc;
    __syncthreads();
    if (grp == 0)
        atomicAdd(&g_pooled[col], s[col] + s[col + 64] + s[col + 128] + s[col + 192]);
}

// ---------------------------------------------------------------------------
// 6. MLP head
// ---------------------------------------------------------------------------
__global__ void head_kernel(const float* __restrict__ W1, const float* __restrict__ b1,
                            const float* __restrict__ W2, const float* __restrict__ b2,
                            float* __restrict__ out) {
    __shared__ float sp[64], sh[64];
    int t = threadIdx.x;
    if (t < 64) sp[t] = g_pooled[t] * (1.0f / (float)N_ATOMS);
    __syncthreads();
    if (t < 64) {
        float a = b1[t];
        #pragma unroll
        for (int k = 0; k < 64; k++) a += sp[k] * W1[k * 64 + t];
        sh[t] = fmaxf(a, 0.0f);
    }
    __syncthreads();
    if (t < 128) {
        float a = b2[t];
        #pragma unroll
        for (int k = 0; k < 64; k++) a += sh[k] * W2[k * 128 + t];
        out[t] = a;
    }
}

// ---------------------------------------------------------------------------
extern "C" void kernel_launch(void* const* d_in, const int* in_sizes, int n_in,
                              void* d_out, int out_size) {
    const int*   an  = (const int*)d_in[0];
    const int*   ei  = (const int*)d_in[3];
    const float* emb = (const float*)d_in[4];
    const float* Wl  = (const float*)d_in[5];
    const float* bl  = (const float*)d_in[6];
    const float* Wg  = (const float*)d_in[7];
    const float* bg  = (const float*)d_in[8];
    const float* W1  = (const float*)d_in[9];
    const float* b1  = (const float*)d_in[10];
    const float* W2  = (const float*)d_in[11];
    const float* b2  = (const float*)d_in[12];
    float* out = (float*)d_out;

    cudaFuncSetAttribute(proj_kernel, cudaFuncAttributeMaxDynamicSharedMemorySize, PROJ_SMEM);

    const int nodeElemBlocks = (N_ATOMS * HID + 255) / 256;   // 25000
    const int projBlocks = (N_ATOMS + 63) / 64;               // 1563
    const int edgeBlocks = (N_EDGES + 255) / 256;             // 3907
    const int gatherBlocks = (N_ATOMS * 32 + 255) / 256;      // 12500

    // Launch order arranged so the profiler (landing on launch index 3)
    // captures proj_kernel. proj layer-0 depends only on embed.
    embed_kernel<<<nodeElemBlocks, 256>>>(an, emb);                        // 0
    hist_kernel<<<edgeBlocks, 256>>>(ei);                                  // 1
    scan_a_kernel<<<SCAN_NB, SCAN_T>>>();                                  // 2
    proj_kernel<<<projBlocks, 256, PROJ_SMEM>>>(Wg, bg, Wl, bl);           // 3 <- profiled
    scan_b_kernel<<<1, 256>>>();                                           // 4
    scan_c_kernel<<<SCAN_NB, SCAN_T>>>();                                  // 5
    scatter_kernel<<<edgeBlocks, 256>>>(ei);                               // 6
    gather_kernel<<<gatherBlocks, 256>>>();                                // 7

    for (int l = 1; l < 3; l++) {
        proj_kernel<<<projBlocks, 256, PROJ_SMEM>>>(Wg + l * 128 * 64, bg + l * 64,
                                                    Wl + l * 64 * 64, bl + l * 64);
        gather_kernel<<<gatherBlocks, 256>>>();
    }
    pool_kernel<<<512, 256>>>();
    head_kernel<<<1, 128>>>(W1, b1, W2, b2, out);
}

// round 4
// speedup vs baseline: 1.9323x; 1.9323x over previous
#include <cuda_runtime.h>
#include <cuda_fp16.h>
#include <cstdint>

// Problem constants
#define N_ATOMS 100000
#define N_EDGES 1000000
#define HID 64
#define OUTD 128

#define SCAN_T 512
#define SCAN_ITEMS (N_ATOMS + 1)
#define SCAN_NB ((SCAN_ITEMS + SCAN_T - 1) / SCAN_T)

// Scratch (device globals: allocation-free rule)
__device__ __half g_xh[N_ATOMS * HID];     // node features, fp16 (MMA A operand)
__device__ float  g_lin[N_ATOMS * HID];    // x @ W_lin + b_lin, fp32 (self term)
__device__ __half g_linh[N_ATOMS * HID];   // same, fp16 (edge messages)
__device__ __half g_gtop[N_ATOMS * HID];   // x @ Wg_top + b_gate
__device__ __half g_gbot[N_ATOMS * HID];   // x @ Wg_bot
__device__ float  g_pooled[HID];

// Edge CSR (built per launch by counting sort)
__device__ int g_cnt[SCAN_ITEMS];
__device__ int g_off[SCAN_ITEMS];
__device__ int g_cur[N_ATOMS];
__device__ int g_part[SCAN_NB];
__device__ int g_scol[N_EDGES];

static __device__ __forceinline__ uint32_t cvta_s(const void* p) {
    uint32_t r;
    asm("{ .reg .u64 t; cvta.to.shared.u64 t, %1; cvt.u32.u64 %0, t; }" : "=r"(r) : "l"(p));
    return r;
}

// ---------------------------------------------------------------------------
// 1. Embedding lookup + zero counters/pooled
// ---------------------------------------------------------------------------
__global__ void __launch_bounds__(256) embed_kernel(const int* __restrict__ an,
                                                    const float* __restrict__ emb) {
    int i = blockIdx.x * 256 + threadIdx.x;
    if (i < N_ATOMS * HID) {
        int v = i >> 6;
        g_xh[i] = __float2half(emb[an[v] * HID + (i & 63)]);
    }
    if (i < SCAN_ITEMS) g_cnt[i] = 0;
    if (i < HID) g_pooled[i] = 0.0f;
}

// ---------------------------------------------------------------------------
// 2. Counting sort of edges by row  (hist -> scan -> scatter)
// ---------------------------------------------------------------------------
__global__ void __launch_bounds__(256) hist_kernel(const int* __restrict__ ei) {
    int e = blockIdx.x * 256 + threadIdx.x;
    if (e < N_EDGES) atomicAdd(&g_cnt[ei[e]], 1);
}

__global__ void __launch_bounds__(SCAN_T) scan_a_kernel() {
    __shared__ int s[SCAN_T];
    int t = threadIdx.x;
    int i = blockIdx.x * SCAN_T + t;
    s[t] = (i < SCAN_ITEMS) ? g_cnt[i] : 0;
    __syncthreads();
    for (int d = SCAN_T / 2; d > 0; d >>= 1) {
        if (t < d) s[t] += s[t + d];
        __syncthreads();
    }
    if (t == 0) g_part[blockIdx.x] = s[0];
}

__global__ void __launch_bounds__(256) scan_b_kernel() {
    __shared__ int s[256];
    int t = threadIdx.x;
    int v = (t < SCAN_NB) ? g_part[t] : 0;
    s[t] = v;
    __syncthreads();
    for (int d = 1; d < 256; d <<= 1) {
        int a = (t >= d) ? s[t - d] : 0;
        __syncthreads();
        s[t] += a;
        __syncthreads();
    }
    if (t < SCAN_NB) g_part[t] = s[t] - v;  // exclusive
}

__global__ void __launch_bounds__(SCAN_T) scan_c_kernel() {
    __shared__ int s[SCAN_T];
    int t = threadIdx.x;
    int i = blockIdx.x * SCAN_T + t;
    int v = (i < SCAN_ITEMS) ? g_cnt[i] : 0;
    s[t] = v;
    __syncthreads();
    for (int d = 1; d < SCAN_T; d <<= 1) {
        int a = (t >= d) ? s[t - d] : 0;
        __syncthreads();
        s[t] += a;
        __syncthreads();
    }
    int off = g_part[blockIdx.x] + s[t] - v;  // exclusive
    if (i < SCAN_ITEMS) g_off[i] = off;
    if (i < N_ATOMS)    g_cur[i] = off;
}

__global__ void __launch_bounds__(256) scatter_kernel(const int* __restrict__ ei) {
    int e = blockIdx.x * 256 + threadIdx.x;
    if (e < N_EDGES) {
        int r = ei[e];
        int c = ei[N_EDGES + e];
        int p = atomicAdd(&g_cur[r], 1);
        g_scol[p] = c;
    }
}

// ---------------------------------------------------------------------------
// 3. Tensor-core projection: [128 nodes/block] x (64 -> 192) fused GEMM.
//    mma.sync m16n8k16 f16.f16->f32. 8 warps = 4(m) x 2(n); warp = 32x96.
//    cols 0..63 -> gtop(+bg, fp16); 64..127 -> gbot(fp16); 128..191 -> lin(+bl).
// ---------------------------------------------------------------------------
#define XS_STRIDE 72    // fp16 elems per A row (128 data + 16B pad -> +4 banks/row)
#define WS_STRIDE 200   // fp16 elems per W row
#define PROJ_SMEM (128 * XS_STRIDE * 2 + 64 * WS_STRIDE * 2 + 128 * 4)

__global__ void __launch_bounds__(256) proj_kernel(const float* __restrict__ Wg,
                                                   const float* __restrict__ bg,
                                                   const float* __restrict__ Wl,
                                                   const float* __restrict__ bl) {
    extern __shared__ __align__(16) char smraw[];
    __half* xs = (__half*)smraw;                                 // [128][72]
    __half* ws = (__half*)(smraw + 128 * XS_STRIDE * 2);         // [64][200]
    float*  bgs = (float*)(smraw + 128 * XS_STRIDE * 2 + 64 * WS_STRIDE * 2);
    float*  bls = bgs + 64;

    const int tid = threadIdx.x;
    const int node0 = blockIdx.x * 128;

    // A tile: 128 rows x 64 fp16, vectorized 16B chunks
    for (int i = tid; i < 128 * 8; i += 256) {
        int r = i >> 3, ch = i & 7;
        int node = node0 + r;
        uint4 v = make_uint4(0u, 0u, 0u, 0u);
        if (node < N_ATOMS)
            v = *reinterpret_cast<const uint4*>(g_xh + (size_t)node * HID + ch * 8);
        *reinterpret_cast<uint4*>(xs + r * XS_STRIDE + ch * 8) = v;
    }
    // fused weights [k][c], c in 0..191
    for (int i = tid; i < 64 * 192; i += 256) {
        int k = i / 192, c = i - k * 192;
        float w;
        if (c < 64)       w = Wg[k * 64 + c];
        else if (c < 128) w = Wg[(64 + k) * 64 + (c - 64)];
        else              w = Wl[k * 64 + (c - 128)];
        ws[k * WS_STRIDE + c] = __float2half(w);
    }
    if (tid < 64) { bgs[tid] = bg[tid]; bls[tid] = bl[tid]; }
    __syncthreads();

    const int wid = tid >> 5, l = tid & 31;
    const int wm = wid & 3;    // 0..3 : rows wm*32 .. +31
    const int wn = wid >> 2;   // 0..1 : cols wn*96 .. +95

    float acc[2][12][4];
    #pragma unroll
    for (int mi = 0; mi < 2; mi++)
        #pragma unroll
        for (int ni = 0; ni < 12; ni++)
            #pragma unroll
            for (int q = 0; q < 4; q++) acc[mi][ni][q] = 0.0f;

    const uint32_t xs_u = cvta_s(xs);
    const uint32_t ws_u = cvta_s(ws);
    // A: lanes 0-15 rows (l&15) at k-half 0; lanes 16-31 same rows at k-half 8
    const uint32_t a_base = xs_u + ((wm * 32 + (l & 15)) * XS_STRIDE + (l >> 4) * 8) * 2;
    // B: lanes 0-15 rows k=(l&15)
    const uint32_t b_base = ws_u + ((l & 15) * WS_STRIDE + wn * 96) * 2;

    #pragma unroll
    for (int kk = 0; kk < 4; kk++) {
        uint32_t b[12][2];
        uint32_t bstep = b_base + kk * 16 * WS_STRIDE * 2;
        #pragma unroll
        for (int ni = 0; ni < 12; ni++) {
            asm volatile("ldmatrix.sync.aligned.m8n8.x2.trans.shared.b16 {%0,%1}, [%2];"
                         : "=r"(b[ni][0]), "=r"(b[ni][1]) : "r"(bstep + ni * 8 * 2));
        }
        uint32_t astep = a_base + kk * 16 * 2;
        #pragma unroll
        for (int mi = 0; mi < 2; mi++) {
            uint32_t a0, a1, a2, a3;
            asm volatile("ldmatrix.sync.aligned.m8n8.x4.shared.b16 {%0,%1,%2,%3}, [%4];"
                         : "=r"(a0), "=r"(a1), "=r"(a2), "=r"(a3)
                         : "r"(astep + mi * 16 * XS_STRIDE * 2));
            #pragma unroll
            for (int ni = 0; ni < 12; ni++) {
                asm volatile(
                    "mma.sync.aligned.m16n8k16.row.col.f32.f16.f16.f32 "
                    "{%0,%1,%2,%3},{%4,%5,%6,%7},{%8,%9},{%0,%1,%2,%3};"
                    : "+f"(acc[mi][ni][0]), "+f"(acc[mi][ni][1]),
                      "+f"(acc[mi][ni][2]), "+f"(acc[mi][ni][3])
                    : "r"(a0), "r"(a1), "r"(a2), "r"(a3), "r"(b[ni][0]), "r"(b[ni][1]));
            }
        }
    }

    // Epilogue: lane l holds cols c=(l&3)*2,+1 ; rows qid=(l>>2), +8.
    const int qid = l >> 2, tig = l & 3;
    #pragma unroll
    for (int mi = 0; mi < 2; mi++) {
        int r0 = node0 + wm * 32 + mi * 16 + qid;
        int r1 = r0 + 8;
        #pragma unroll
        for (int ni = 0; ni < 12; ni++) {
            int c = wn * 96 + ni * 8 + tig * 2;
            float d0 = acc[mi][ni][0], d1 = acc[mi][ni][1];
            float d2 = acc[mi][ni][2], d3 = acc[mi][ni][3];
            if (c < 64) {
                float b0v = bgs[c], b1v = bgs[c + 1];
                if (r0 < N_ATOMS)
                    *reinterpret_cast<__half2*>(g_gtop + (size_t)r0 * HID + c) =
                        __floats2half2_rn(d0 + b0v, d1 + b1v);
                if (r1 < N_ATOMS)
                    *reinterpret_cast<__half2*>(g_gtop + (size_t)r1 * HID + c) =
                        __floats2half2_rn(d2 + b0v, d3 + b1v);
            } else if (c < 128) {
                int cc = c - 64;
                if (r0 < N_ATOMS)
                    *reinterpret_cast<__half2*>(g_gbot + (size_t)r0 * HID + cc) =
                        __floats2half2_rn(d0, d1);
                if (r1 < N_ATOMS)
                    *reinterpret_cast<__half2*>(g_gbot + (size_t)r1 * HID + cc) =
                        __floats2half2_rn(d2, d3);
            } else {
                int cc = c - 128;
                float b0v = bls[cc], b1v = bls[cc + 1];
                float e0 = d0 + b0v, e1 = d1 + b1v, e2 = d2 + b0v, e3 = d3 + b1v;
                if (r0 < N_ATOMS) {
                    *reinterpret_cast<float2*>(g_lin + (size_t)r0 * HID + cc) = make_float2(e0, e1);
                    *reinterpret_cast<__half2*>(g_linh + (size_t)r0 * HID + cc) = __floats2half2_rn(e0, e1);
                }
                if (r1 < N_ATOMS) {
                    *reinterpret_cast<float2*>(g_lin + (size_t)r1 * HID + cc) = make_float2(e2, e3);
                    *reinterpret_cast<__half2*>(g_linh + (size_t)r1 * HID + cc) = __floats2half2_rn(e2, e3);
                }
            }
        }
    }
}

// ---------------------------------------------------------------------------
// 4. Gather-aggregate + fused node update (round-2 structure, tanh sigmoid).
//    x[v] = relu( lin[v] + sum_{c in N(v)} sigmoid(gtop[v]+gbot[c]) * linh[c] )
// ---------------------------------------------------------------------------
__global__ void __launch_bounds__(256) gather_kernel() {
    int w = (blockIdx.x * 256 + threadIdx.x) >> 5;
    int l = threadIdx.x & 31;
    if (w >= N_ATOMS) return;

    int beg = __ldg(&g_off[w]);
    int end = __ldg(&g_off[w + 1]);

    const __half2* gt2 = reinterpret_cast<const __half2*>(g_gtop);
    const __half2* gb2 = reinterpret_cast<const __half2*>(g_gbot);
    const __half2* lh2 = reinterpret_cast<const __half2*>(g_linh);

    float2 gtf = __half22float2(gt2[(size_t)w * 32 + l]);
    float2 acc = *reinterpret_cast<const float2*>(g_lin + (size_t)w * HID + 2 * l);

    for (int base = beg; base < end; base += 32) {
        int myc = (base + l < end) ? g_scol[base + l] : 0;
        int m = min(32, end - base);
        #pragma unroll 4
        for (int j = 0; j < m; j++) {
            int cc = __shfl_sync(0xffffffffu, myc, j);
            float2 gbf = __half22float2(gb2[(size_t)cc * 32 + l]);
            float2 lhf = __half22float2(lh2[(size_t)cc * 32 + l]);
            float t0, t1;
            asm("tanh.approx.f32 %0, %1;" : "=f"(t0) : "f"(0.5f * (gtf.x + gbf.x)));
            asm("tanh.approx.f32 %0, %1;" : "=f"(t1) : "f"(0.5f * (gtf.y + gbf.y)));
            acc.x += (0.5f * t0 + 0.5f) * lhf.x;
            acc.y += (0.5f * t1 + 0.5f) * lhf.y;
        }
    }

    __half2* xo = reinterpret_cast<__half2*>(g_xh);
    xo[(size_t)w * 32 + l] = __floats2half2_rn(fmaxf(acc.x, 0.0f), fmaxf(acc.y, 0.0f));
}

// ---------------------------------------------------------------------------
// 5. Mean pool (sum; mean applied in head)
// ---------------------------------------------------------------------------
__global__ void __launch_bounds__(256) pool_kernel() {
    int t = threadIdx.x;
    int col = t & 63;
    int grp = t >> 6;
    float acc = 0.0f;
    for (int node = blockIdx.x * 4 + grp; node < N_ATOMS; node += gridDim.x * 4)
        acc += __half2float(g_xh[(size_t)node * HID + col]);
    __shared__ float s[256];
    s[t] = acc;
    __syncthreads();
    if (grp == 0)
        atomicAdd(&g_pooled[col], s[col] + s[col + 64] + s[col + 128] + s[col + 192]);
}

// ---------------------------------------------------------------------------
// 6. MLP head
// ---------------------------------------------------------------------------
__global__ void head_kernel(const float* __restrict__ W1, const float* __restrict__ b1,
                            const float* __restrict__ W2, const float* __restrict__ b2,
                            float* __restrict__ out) {
    __shared__ float sp[64], sh[64];
    int t = threadIdx.x;
    if (t < 64) sp[t] = g_pooled[t] * (1.0f / (float)N_ATOMS);
    __syncthreads();
    if (t < 64) {
        float a = b1[t];
        #pragma unroll
        for (int k = 0; k < 64; k++) a += sp[k] * W1[k * 64 + t];
        sh[t] = fmaxf(a, 0.0f);
    }
    __syncthreads();
    if (t < 128) {
        float a = b2[t];
        #pragma unroll
        for (int k = 0; k < 64; k++) a += sh[k] * W2[k * 128 + t];
        out[t] = a;
    }
}

// ---------------------------------------------------------------------------
extern "C" void kernel_launch(void* const* d_in, const int* in_sizes, int n_in,
                              void* d_out, int out_size) {
    const int*   an  = (const int*)d_in[0];
    const int*   ei  = (const int*)d_in[3];
    const float* emb = (const float*)d_in[4];
    const float* Wl  = (const float*)d_in[5];
    const float* bl  = (const float*)d_in[6];
    const float* Wg  = (const float*)d_in[7];
    const float* bg  = (const float*)d_in[8];
    const float* W1  = (const float*)d_in[9];
    const float* b1  = (const float*)d_in[10];
    const float* W2  = (const float*)d_in[11];
    const float* b2  = (const float*)d_in[12];
    float* out = (float*)d_out;

    cudaFuncSetAttribute(proj_kernel, cudaFuncAttributeMaxDynamicSharedMemorySize, PROJ_SMEM);

    const int nodeElemBlocks = (N_ATOMS * HID + 255) / 256;   // 25000
    const int projBlocks = (N_ATOMS + 127) / 128;             // 782
    const int edgeBlocks = (N_EDGES + 255) / 256;             // 3907
    const int gatherBlocks = (N_ATOMS * 32 + 255) / 256;      // 12500

    // proj layer-0 placed at launch index 3 (profiler lands there).
    embed_kernel<<<nodeElemBlocks, 256>>>(an, emb);                        // 0
    hist_kernel<<<edgeBlocks, 256>>>(ei);                                  // 1
    scan_a_kernel<<<SCAN_NB, SCAN_T>>>();                                  // 2
    proj_kernel<<<projBlocks, 256, PROJ_SMEM>>>(Wg, bg, Wl, bl);           // 3 <- profiled
    scan_b_kernel<<<1, 256>>>();                                           // 4
    scan_c_kernel<<<SCAN_NB, SCAN_T>>>();                                  // 5
    scatter_kernel<<<edgeBlocks, 256>>>(ei);                               // 6
    gather_kernel<<<gatherBlocks, 256>>>();                                // 7

    for (int l = 1; l < 3; l++) {
        proj_kernel<<<projBlocks, 256, PROJ_SMEM>>>(Wg + l * 128 * 64, bg + l * 64,
                                                    Wl + l * 64 * 64, bl + l * 64);
        gather_kernel<<<gatherBlocks, 256>>>();
    }
    pool_kernel<<<512, 256>>>();
    head_kernel<<<1, 128>>>(W1, b1, W2, b2, out);
}

// round 5
// speedup vs baseline: 2.3318x; 1.2068x over previous
#include <cuda_runtime.h>
#include <cuda_fp16.h>
#include <cstdint>

// Problem constants
#define N_ATOMS 100000
#define N_EDGES 1000000
#define HID 64
#define OUTD 128

#define SCAN_T 512
#define SCAN_ITEMS (N_ATOMS + 1)
#define SCAN_NB ((SCAN_ITEMS + SCAN_T - 1) / SCAN_T)

// Scratch (device globals: allocation-free rule)
__device__ __half g_xh[N_ATOMS * HID];     // node features, fp16 (MMA A operand)
__device__ float  g_lin[N_ATOMS * HID];    // x @ W_lin + b_lin, fp32 (self term)
__device__ __half g_linh[N_ATOMS * HID];   // same, fp16 (edge messages)
__device__ __half g_gtop[N_ATOMS * HID];   // x @ Wg_top + b_gate
__device__ __half g_gbot[N_ATOMS * HID];   // x @ Wg_bot
__device__ float  g_pooled[HID];

// Edge CSR (built per launch by counting sort)
__device__ int g_cnt[SCAN_ITEMS];
__device__ int g_off[SCAN_ITEMS];
__device__ int g_cur[N_ATOMS];
__device__ int g_part[SCAN_NB];
__device__ int g_scol[N_EDGES];

static __device__ __forceinline__ uint32_t cvta_s(const void* p) {
    uint32_t r;
    asm("{ .reg .u64 t; cvta.to.shared.u64 t, %1; cvt.u32.u64 %0, t; }" : "=r"(r) : "l"(p));
    return r;
}

// ---------------------------------------------------------------------------
// 1. Embedding lookup + zero counters/pooled
// ---------------------------------------------------------------------------
__global__ void __launch_bounds__(256) embed_kernel(const int* __restrict__ an,
                                                    const float* __restrict__ emb) {
    int i = blockIdx.x * 256 + threadIdx.x;
    if (i < N_ATOMS * HID) {
        int v = i >> 6;
        g_xh[i] = __float2half(emb[an[v] * HID + (i & 63)]);
    }
    if (i < SCAN_ITEMS) g_cnt[i] = 0;
    if (i < HID) g_pooled[i] = 0.0f;
}

// ---------------------------------------------------------------------------
// 2. Counting sort of edges by row  (hist -> scan -> scatter)
// ---------------------------------------------------------------------------
__global__ void __launch_bounds__(256) hist_kernel(const int* __restrict__ ei) {
    int e = blockIdx.x * 256 + threadIdx.x;
    if (e < N_EDGES) atomicAdd(&g_cnt[ei[e]], 1);
}

__global__ void __launch_bounds__(SCAN_T) scan_a_kernel() {
    __shared__ int s[SCAN_T];
    int t = threadIdx.x;
    int i = blockIdx.x * SCAN_T + t;
    s[t] = (i < SCAN_ITEMS) ? g_cnt[i] : 0;
    __syncthreads();
    for (int d = SCAN_T / 2; d > 0; d >>= 1) {
        if (t < d) s[t] += s[t + d];
        __syncthreads();
    }
    if (t == 0) g_part[blockIdx.x] = s[0];
}

__global__ void __launch_bounds__(256) scan_b_kernel() {
    __shared__ int s[256];
    int t = threadIdx.x;
    int v = (t < SCAN_NB) ? g_part[t] : 0;
    s[t] = v;
    __syncthreads();
    for (int d = 1; d < 256; d <<= 1) {
        int a = (t >= d) ? s[t - d] : 0;
        __syncthreads();
        s[t] += a;
        __syncthreads();
    }
    if (t < SCAN_NB) g_part[t] = s[t] - v;  // exclusive
}

__global__ void __launch_bounds__(SCAN_T) scan_c_kernel() {
    __shared__ int s[SCAN_T];
    int t = threadIdx.x;
    int i = blockIdx.x * SCAN_T + t;
    int v = (i < SCAN_ITEMS) ? g_cnt[i] : 0;
    s[t] = v;
    __syncthreads();
    for (int d = 1; d < SCAN_T; d <<= 1) {
        int a = (t >= d) ? s[t - d] : 0;
        __syncthreads();
        s[t] += a;
        __syncthreads();
    }
    int off = g_part[blockIdx.x] + s[t] - v;  // exclusive
    if (i < SCAN_ITEMS) g_off[i] = off;
    if (i < N_ATOMS)    g_cur[i] = off;
}

__global__ void __launch_bounds__(256) scatter_kernel(const int* __restrict__ ei) {
    int e = blockIdx.x * 256 + threadIdx.x;
    if (e < N_EDGES) {
        int r = ei[e];
        int c = ei[N_EDGES + e];
        int p = atomicAdd(&g_cur[r], 1);
        g_scol[p] = c;
    }
}

// ---------------------------------------------------------------------------
// 3. Tensor-core projection: 512 threads, [128 nodes/block] x (64 -> 192).
//    16 warps = 4(m) x 4(n); warp tile = 32 x 48 (2 x 6 mma frags).
//    Epilogue staged through smem for fully coalesced 16B global stores.
// ---------------------------------------------------------------------------
#define XS_STRIDE 72    // fp16 elems per A row
#define WS_STRIDE 200   // fp16 elems per W row
#define STG_STRIDE 72   // staging stride (halves for gt/gb, floats for lin)
#define PROJ_OPERAND_BYTES (128 * XS_STRIDE * 2 + 64 * WS_STRIDE * 2)   // 44032
#define PROJ_STAGE_BYTES   (128 * STG_STRIDE * 2 * 2 + 128 * STG_STRIDE * 4) // 73728
#define PROJ_BIAS_OFF      PROJ_STAGE_BYTES
#define PROJ_SMEM          (PROJ_STAGE_BYTES + 128 * 4)

__global__ void __launch_bounds__(512) proj_kernel(const float* __restrict__ Wg,
                                                   const float* __restrict__ bg,
                                                   const float* __restrict__ Wl,
                                                   const float* __restrict__ bl) {
    extern __shared__ __align__(16) char smraw[];
    __half* xs = (__half*)smraw;                                 // [128][72]
    __half* ws = (__half*)(smraw + 128 * XS_STRIDE * 2);         // [64][200]
    // staging region (reuses operand space after main loop):
    __half* sg_gt = (__half*)smraw;                              // [128][72]
    __half* sg_gb = (__half*)(smraw + 128 * STG_STRIDE * 2);     // [128][72]
    float*  sg_ln = (float*)(smraw + 128 * STG_STRIDE * 2 * 2);  // [128][72]
    float*  bgs = (float*)(smraw + PROJ_BIAS_OFF);
    float*  bls = bgs + 64;

    const int tid = threadIdx.x;
    const int node0 = blockIdx.x * 128;

    // A tile: 128 rows x 64 fp16, 16B chunks
    for (int i = tid; i < 128 * 8; i += 512) {
        int r = i >> 3, ch = i & 7;
        int node = node0 + r;
        uint4 v = make_uint4(0u, 0u, 0u, 0u);
        if (node < N_ATOMS)
            v = *reinterpret_cast<const uint4*>(g_xh + (size_t)node * HID + ch * 8);
        *reinterpret_cast<uint4*>(xs + r * XS_STRIDE + ch * 8) = v;
    }
    // fused weights [k][c], c in 0..191
    for (int i = tid; i < 64 * 192; i += 512) {
        int k = i / 192, c = i - k * 192;
        float w;
        if (c < 64)       w = Wg[k * 64 + c];
        else if (c < 128) w = Wg[(64 + k) * 64 + (c - 64)];
        else              w = Wl[k * 64 + (c - 128)];
        ws[k * WS_STRIDE + c] = __float2half(w);
    }
    if (tid < 64) { bgs[tid] = bg[tid]; bls[tid] = bl[tid]; }
    __syncthreads();

    const int wid = tid >> 5, l = tid & 31;
    const int wm = wid & 3;    // rows wm*32 .. +31
    const int wn = wid >> 2;   // cols wn*48 .. +47

    float acc[2][6][4];
    #pragma unroll
    for (int mi = 0; mi < 2; mi++)
        #pragma unroll
        for (int ni = 0; ni < 6; ni++)
            #pragma unroll
            for (int q = 0; q < 4; q++) acc[mi][ni][q] = 0.0f;

    const uint32_t xs_u = cvta_s(xs);
    const uint32_t ws_u = cvta_s(ws);
    const uint32_t a_base = xs_u + ((wm * 32 + (l & 15)) * XS_STRIDE + (l >> 4) * 8) * 2;
    const uint32_t b_base = ws_u + ((l & 15) * WS_STRIDE + wn * 48) * 2;

    #pragma unroll
    for (int kk = 0; kk < 4; kk++) {
        uint32_t b[6][2];
        uint32_t bstep = b_base + kk * 16 * WS_STRIDE * 2;
        #pragma unroll
        for (int ni = 0; ni < 6; ni++) {
            asm volatile("ldmatrix.sync.aligned.m8n8.x2.trans.shared.b16 {%0,%1}, [%2];"
                         : "=r"(b[ni][0]), "=r"(b[ni][1]) : "r"(bstep + ni * 8 * 2));
        }
        uint32_t astep = a_base + kk * 16 * 2;
        #pragma unroll
        for (int mi = 0; mi < 2; mi++) {
            uint32_t a0, a1, a2, a3;
            asm volatile("ldmatrix.sync.aligned.m8n8.x4.shared.b16 {%0,%1,%2,%3}, [%4];"
                         : "=r"(a0), "=r"(a1), "=r"(a2), "=r"(a3)
                         : "r"(astep + mi * 16 * XS_STRIDE * 2));
            #pragma unroll
            for (int ni = 0; ni < 6; ni++) {
                asm volatile(
                    "mma.sync.aligned.m16n8k16.row.col.f32.f16.f16.f32 "
                    "{%0,%1,%2,%3},{%4,%5,%6,%7},{%8,%9},{%0,%1,%2,%3};"
                    : "+f"(acc[mi][ni][0]), "+f"(acc[mi][ni][1]),
                      "+f"(acc[mi][ni][2]), "+f"(acc[mi][ni][3])
                    : "r"(a0), "r"(a1), "r"(a2), "r"(a3), "r"(b[ni][0]), "r"(b[ni][1]));
            }
        }
    }

    __syncthreads();   // operand smem dead; reuse as staging

    // Stage fragments to smem (conflict-free: stride 72)
    const int qid = l >> 2, tig = l & 3;
    #pragma unroll
    for (int mi = 0; mi < 2; mi++) {
        int r0 = wm * 32 + mi * 16 + qid;   // local row
        int r1 = r0 + 8;
        #pragma unroll
        for (int ni = 0; ni < 6; ni++) {
            int c = wn * 48 + ni * 8 + tig * 2;
            float d0 = acc[mi][ni][0], d1 = acc[mi][ni][1];
            float d2 = acc[mi][ni][2], d3 = acc[mi][ni][3];
            if (c < 64) {
                float b0v = bgs[c], b1v = bgs[c + 1];
                *reinterpret_cast<__half2*>(sg_gt + r0 * STG_STRIDE + c) = __floats2half2_rn(d0 + b0v, d1 + b1v);
                *reinterpret_cast<__half2*>(sg_gt + r1 * STG_STRIDE + c) = __floats2half2_rn(d2 + b0v, d3 + b1v);
            } else if (c < 128) {
                int cc = c - 64;
                *reinterpret_cast<__half2*>(sg_gb + r0 * STG_STRIDE + cc) = __floats2half2_rn(d0, d1);
                *reinterpret_cast<__half2*>(sg_gb + r1 * STG_STRIDE + cc) = __floats2half2_rn(d2, d3);
            } else {
                int cc = c - 128;
                float b0v = bls[cc], b1v = bls[cc + 1];
                *reinterpret_cast<float2*>(sg_ln + r0 * STG_STRIDE + cc) = make_float2(d0 + b0v, d1 + b1v);
                *reinterpret_cast<float2*>(sg_ln + r1 * STG_STRIDE + cc) = make_float2(d2 + b0v, d3 + b1v);
            }
        }
    }
    __syncthreads();

    // Coalesced write-out: uint4 chunks
    // gtop/gbot: 1024 chunks of 8 halves each
    #pragma unroll
    for (int p = 0; p < 2; p++) {
        int cidx = tid + p * 512;
        int r = cidx >> 3, grp = cidx & 7;
        int node = node0 + r;
        if (node < N_ATOMS) {
            uint4 vt = *reinterpret_cast<uint4*>(sg_gt + r * STG_STRIDE + grp * 8);
            uint4 vb = *reinterpret_cast<uint4*>(sg_gb + r * STG_STRIDE + grp * 8);
            *reinterpret_cast<uint4*>(g_gtop + (size_t)node * HID + grp * 8) = vt;
            *reinterpret_cast<uint4*>(g_gbot + (size_t)node * HID + grp * 8) = vb;
        }
    }
    // lin fp32: 2048 chunks of 4 floats; linh: convert pairs
    #pragma unroll
    for (int p = 0; p < 4; p++) {
        int cidx = tid + p * 512;
        int r = cidx >> 4, grp = cidx & 15;
        int node = node0 + r;
        if (node < N_ATOMS) {
            float4 v = *reinterpret_cast<float4*>(sg_ln + r * STG_STRIDE + grp * 4);
            *reinterpret_cast<float4*>(g_lin + (size_t)node * HID + grp * 4) = v;
            __half2 h0 = __floats2half2_rn(v.x, v.y);
            __half2 h1 = __floats2half2_rn(v.z, v.w);
            *reinterpret_cast<__half2*>(g_linh + (size_t)node * HID + grp * 4) = h0;
            *reinterpret_cast<__half2*>(g_linh + (size_t)node * HID + grp * 4 + 2) = h1;
        }
    }
}

// ---------------------------------------------------------------------------
// 4. Gather-aggregate + fused node update.
//    x[v] = relu( lin[v] + sum_{c in N(v)} sigmoid(gtop[v]+gbot[c]) * linh[c] )
// ---------------------------------------------------------------------------
__global__ void __launch_bounds__(256) gather_kernel() {
    int w = (blockIdx.x * 256 + threadIdx.x) >> 5;
    int l = threadIdx.x & 31;
    if (w >= N_ATOMS) return;

    int beg = __ldg(&g_off[w]);
    int end = __ldg(&g_off[w + 1]);

    const __half2* gt2 = reinterpret_cast<const __half2*>(g_gtop);
    const __half2* gb2 = reinterpret_cast<const __half2*>(g_gbot);
    const __half2* lh2 = reinterpret_cast<const __half2*>(g_linh);

    float2 gtf = __half22float2(gt2[(size_t)w * 32 + l]);
    float2 acc = *reinterpret_cast<const float2*>(g_lin + (size_t)w * HID + 2 * l);

    for (int base = beg; base < end; base += 32) {
        int myc = (base + l < end) ? g_scol[base + l] : 0;
        int m = min(32, end - base);
        #pragma unroll 4
        for (int j = 0; j < m; j++) {
            int cc = __shfl_sync(0xffffffffu, myc, j);
            float2 gbf = __half22float2(gb2[(size_t)cc * 32 + l]);
            float2 lhf = __half22float2(lh2[(size_t)cc * 32 + l]);
            float t0, t1;
            asm("tanh.approx.f32 %0, %1;" : "=f"(t0) : "f"(0.5f * (gtf.x + gbf.x)));
            asm("tanh.approx.f32 %0, %1;" : "=f"(t1) : "f"(0.5f * (gtf.y + gbf.y)));
            acc.x += (0.5f * t0 + 0.5f) * lhf.x;
            acc.y += (0.5f * t1 + 0.5f) * lhf.y;
        }
    }

    __half2* xo = reinterpret_cast<__half2*>(g_xh);
    xo[(size_t)w * 32 + l] = __floats2half2_rn(fmaxf(acc.x, 0.0f), fmaxf(acc.y, 0.0f));
}

// ---------------------------------------------------------------------------
// 5. Mean pool
// ---------------------------------------------------------------------------
__global__ void __launch_bounds__(256) pool_kernel() {
    int t = threadIdx.x;
    int col = t & 63;
    int grp = t >> 6;
    float acc = 0.0f;
    for (int node = blockIdx.x * 4 + grp; node < N_ATOMS; node += gridDim.x * 4)
        acc += __half2float(g_xh[(size_t)node * HID + col]);
    __shared__ float s[256];
    s[t] = acc;
    __syncthreads();
    if (grp == 0)
        atomicAdd(&g_pooled[col], s[col] + s[col + 64] + s[col + 128] + s[col + 192]);
}

// ---------------------------------------------------------------------------
// 6. MLP head
// ---------------------------------------------------------------------------
__global__ void head_kernel(const float* __restrict__ W1, const float* __restrict__ b1,
                            const float* __restrict__ W2, const float* __restrict__ b2,
                            float* __restrict__ out) {
    __shared__ float sp[64], sh[64];
    int t = threadIdx.x;
    if (t < 64) sp[t] = g_pooled[t] * (1.0f / (float)N_ATOMS);
    __syncthreads();
    if (t < 64) {
        float a = b1[t];
        #pragma unroll
        for (int k = 0; k < 64; k++) a += sp[k] * W1[k * 64 + t];
        sh[t] = fmaxf(a, 0.0f);
    }
    __syncthreads();
    if (t < 128) {
        float a = b2[t];
        #pragma unroll
        for (int k = 0; k < 64; k++) a += sh[k] * W2[k * 128 + t];
        out[t] = a;
    }
}

// ---------------------------------------------------------------------------
extern "C" void kernel_launch(void* const* d_in, const int* in_sizes, int n_in,
                              void* d_out, int out_size) {
    const int*   an  = (const int*)d_in[0];
    const int*   ei  = (const int*)d_in[3];
    const float* emb = (const float*)d_in[4];
    const float* Wl  = (const float*)d_in[5];
    const float* bl  = (const float*)d_in[6];
    const float* Wg  = (const float*)d_in[7];
    const float* bg  = (const float*)d_in[8];
    const float* W1  = (const float*)d_in[9];
    const float* b1  = (const float*)d_in[10];
    const float* W2  = (const float*)d_in[11];
    const float* b2  = (const float*)d_in[12];
    float* out = (float*)d_out;

    cudaFuncSetAttribute(proj_kernel, cudaFuncAttributeMaxDynamicSharedMemorySize, PROJ_SMEM);

    const int nodeElemBlocks = (N_ATOMS * HID + 255) / 256;   // 25000
    const int projBlocks = (N_ATOMS + 127) / 128;             // 782
    const int edgeBlocks = (N_EDGES + 255) / 256;             // 3907
    const int gatherBlocks = (N_ATOMS * 32 + 255) / 256;      // 12500

    // proj layer-0 at launch index 3 (profiler lands there).
    embed_kernel<<<nodeElemBlocks, 256>>>(an, emb);                        // 0
    hist_kernel<<<edgeBlocks, 256>>>(ei);                                  // 1
    scan_a_kernel<<<SCAN_NB, SCAN_T>>>();                                  // 2
    proj_kernel<<<projBlocks, 512, PROJ_SMEM>>>(Wg, bg, Wl, bl);           // 3 <- profiled
    scan_b_kernel<<<1, 256>>>();                                           // 4
    scan_c_kernel<<<SCAN_NB, SCAN_T>>>();                                  // 5
    scatter_kernel<<<edgeBlocks, 256>>>(ei);                               // 6
    gather_kernel<<<gatherBlocks, 256>>>();                                // 7

    for (int l = 1; l < 3; l++) {
        proj_kernel<<<projBlocks, 512, PROJ_SMEM>>>(Wg + l * 128 * 64, bg + l * 64,
                                                    Wl + l * 64 * 64, bl + l * 64);
        gather_kernel<<<gatherBlocks, 256>>>();
    }
    pool_kernel<<<512, 256>>>();
    head_kernel<<<1, 128>>>(W1, b1, W2, b2, out);
}

// round 6
// speedup vs baseline: 2.9823x; 1.2789x over previous
#include <cuda_runtime.h>
#include <cuda_fp16.h>
#include <cstdint>

// Problem constants
#define N_ATOMS 100000
#define N_EDGES 1000000
#define HID 64
#define OUTD 128
#define NTILES 782           // ceil(N_ATOMS / 128)
#define PROJ_GRID 148

#define SCAN_T 512
#define SCAN_ITEMS (N_ATOMS + 1)
#define SCAN_NB ((SCAN_ITEMS + SCAN_T - 1) / SCAN_T)

// Scratch (device globals: allocation-free rule)
__device__ __half g_xh[N_ATOMS * HID];     // node features, fp16 (MMA A operand)
__device__ float  g_lin[N_ATOMS * HID];    // x @ W_lin + b_lin, fp32 (self term)
__device__ __half g_linh[N_ATOMS * HID];   // same, fp16 (edge messages)
__device__ __half g_gtop[N_ATOMS * HID];   // x @ Wg_top + b_gate
__device__ __half g_gbot[N_ATOMS * HID];   // x @ Wg_bot
__device__ __half g_wf[3 * 64 * 192];      // fused fp16 weights per layer
__device__ float  g_pooled[HID];

// Edge CSR (built per launch by counting sort)
__device__ int g_cnt[SCAN_ITEMS];
__device__ int g_off[SCAN_ITEMS];
__device__ int g_cur[N_ATOMS];
__device__ int g_part[SCAN_NB];
__device__ int g_scol[N_EDGES];

static __device__ __forceinline__ uint32_t cvta_s(const void* p) {
    uint32_t r;
    asm("{ .reg .u64 t; cvta.to.shared.u64 t, %1; cvt.u32.u64 %0, t; }" : "=r"(r) : "l"(p));
    return r;
}

// ---------------------------------------------------------------------------
// 0. Weight preconvert: fused fp16 layout [layer][k=64][c=192]
//    c 0..63 = Wg_top[k][c], 64..127 = Wg_bot[k][c-64], 128..191 = Wl[k][c-128]
// ---------------------------------------------------------------------------
__global__ void __launch_bounds__(256) wconv_kernel(const float* __restrict__ Wg,
                                                    const float* __restrict__ Wl) {
    int i = blockIdx.x * 256 + threadIdx.x;
    if (i < 3 * 64 * 192) {
        int lay = i / (64 * 192);
        int rem = i - lay * (64 * 192);
        int k = rem / 192, c = rem - k * 192;
        float w;
        if (c < 64)       w = Wg[lay * 128 * 64 + k * 64 + c];
        else if (c < 128) w = Wg[lay * 128 * 64 + (64 + k) * 64 + (c - 64)];
        else              w = Wl[lay * 64 * 64 + k * 64 + (c - 128)];
        g_wf[i] = __float2half(w);
    }
}

// ---------------------------------------------------------------------------
// 1. Embedding lookup + zero counters/pooled
// ---------------------------------------------------------------------------
__global__ void __launch_bounds__(256) embed_kernel(const int* __restrict__ an,
                                                    const float* __restrict__ emb) {
    int i = blockIdx.x * 256 + threadIdx.x;
    if (i < N_ATOMS * HID) {
        int v = i >> 6;
        g_xh[i] = __float2half(emb[an[v] * HID + (i & 63)]);
    }
    if (i < SCAN_ITEMS) g_cnt[i] = 0;
    if (i < HID) g_pooled[i] = 0.0f;
}

// ---------------------------------------------------------------------------
// 2. Counting sort of edges by row  (hist -> scan -> scatter)
// ---------------------------------------------------------------------------
__global__ void __launch_bounds__(256) hist_kernel(const int* __restrict__ ei) {
    int e = blockIdx.x * 256 + threadIdx.x;
    if (e < N_EDGES) atomicAdd(&g_cnt[ei[e]], 1);
}

__global__ void __launch_bounds__(SCAN_T) scan_a_kernel() {
    __shared__ int s[SCAN_T];
    int t = threadIdx.x;
    int i = blockIdx.x * SCAN_T + t;
    s[t] = (i < SCAN_ITEMS) ? g_cnt[i] : 0;
    __syncthreads();
    for (int d = SCAN_T / 2; d > 0; d >>= 1) {
        if (t < d) s[t] += s[t + d];
        __syncthreads();
    }
    if (t == 0) g_part[blockIdx.x] = s[0];
}

__global__ void __launch_bounds__(256) scan_b_kernel() {
    __shared__ int s[256];
    int t = threadIdx.x;
    int v = (t < SCAN_NB) ? g_part[t] : 0;
    s[t] = v;
    __syncthreads();
    for (int d = 1; d < 256; d <<= 1) {
        int a = (t >= d) ? s[t - d] : 0;
        __syncthreads();
        s[t] += a;
        __syncthreads();
    }
    if (t < SCAN_NB) g_part[t] = s[t] - v;  // exclusive
}

__global__ void __launch_bounds__(SCAN_T) scan_c_kernel() {
    __shared__ int s[SCAN_T];
    int t = threadIdx.x;
    int i = blockIdx.x * SCAN_T + t;
    int v = (i < SCAN_ITEMS) ? g_cnt[i] : 0;
    s[t] = v;
    __syncthreads();
    for (int d = 1; d < SCAN_T; d <<= 1) {
        int a = (t >= d) ? s[t - d] : 0;
        __syncthreads();
        s[t] += a;
        __syncthreads();
    }
    int off = g_part[blockIdx.x] + s[t] - v;  // exclusive
    if (i < SCAN_ITEMS) g_off[i] = off;
    if (i < N_ATOMS)    g_cur[i] = off;
}

__global__ void __launch_bounds__(256) scatter_kernel(const int* __restrict__ ei) {
    int e = blockIdx.x * 256 + threadIdx.x;
    if (e < N_EDGES) {
        int r = ei[e];
        int c = ei[N_EDGES + e];
        int p = atomicAdd(&g_cur[r], 1);
        g_scol[p] = c;
    }
}

// ---------------------------------------------------------------------------
// 3. Persistent tensor-core projection.
//    grid=148, 512 thr. Weights loaded to smem ONCE per block; tiles of 128
//    nodes streamed with cp.async double buffering. 16 warps = 4(m) x 4(n).
// ---------------------------------------------------------------------------
#define WS_STRIDE 200
#define XS_STRIDE 72
#define STG_STRIDE 72
#define WS_BYTES   (64 * WS_STRIDE * 2)          // 25600
#define XS_OFF     WS_BYTES
#define XS_BUF_BYTES (128 * XS_STRIDE * 2)       // 18432
#define STG_OFF    (XS_OFF + 2 * XS_BUF_BYTES)   // 62464
#define SG_GT_OFF  STG_OFF
#define SG_GB_OFF  (STG_OFF + 128 * STG_STRIDE * 2)
#define SG_LN_OFF  (STG_OFF + 2 * 128 * STG_STRIDE * 2)
#define BIAS_OFF   (STG_OFF + 128 * STG_STRIDE * 8)  // after gt+gb (2x18432) + ln (36864)
#define PROJ_SMEM  (BIAS_OFF + 512)

static __device__ __forceinline__ void prefetch_tile(int tile, int buf, int tid,
                                                     uint32_t xs_base_u) {
    int n0 = tile * 128;
    #pragma unroll
    for (int p = 0; p < 2; p++) {
        int idx = tid + p * 512;
        int r = idx >> 3, grp = idx & 7;
        int node = n0 + r;
        int node_c = node < N_ATOMS ? node : N_ATOMS - 1;
        uint32_t dst = xs_base_u + buf * XS_BUF_BYTES + (r * XS_STRIDE + grp * 8) * 2;
        const void* src = g_xh + (size_t)node_c * HID + grp * 8;
        int sz = (node < N_ATOMS) ? 16 : 0;
        asm volatile("cp.async.cg.shared.global [%0], [%1], 16, %2;"
                     :: "r"(dst), "l"(src), "r"(sz));
    }
    asm volatile("cp.async.commit_group;");
}

__global__ void __launch_bounds__(512) proj_kernel(int layer,
                                                   const float* __restrict__ bg,
                                                   const float* __restrict__ bl) {
    extern __shared__ __align__(16) char smraw[];
    __half* ws   = (__half*)smraw;                    // [64][200]
    __half* sg_gt = (__half*)(smraw + SG_GT_OFF);     // [128][72]
    __half* sg_gb = (__half*)(smraw + SG_GB_OFF);     // [128][72]
    float*  sg_ln = (float*)(smraw + SG_LN_OFF);      // [128][72]
    float*  bgs  = (float*)(smraw + BIAS_OFF);
    float*  bls  = bgs + 64;

    const int tid = threadIdx.x;
    const __half* wf = g_wf + layer * 64 * 192;

    // fused fp16 weights -> smem [64][200], 16B chunks (once per block)
    for (int i = tid; i < 1536; i += 512) {
        int k = i / 24, grp = i - k * 24;
        *reinterpret_cast<uint4*>(ws + k * WS_STRIDE + grp * 8) =
            *reinterpret_cast<const uint4*>(wf + k * 192 + grp * 8);
    }
    if (tid < 64) { bgs[tid] = bg[tid]; bls[tid] = bl[tid]; }

    const uint32_t xs_base_u = cvta_s(smraw + XS_OFF);
    const uint32_t ws_u = cvta_s(ws);

    const int wid = tid >> 5, l = tid & 31;
    const int wm = wid & 3;    // rows wm*32 .. +31
    const int wn = wid >> 2;   // cols wn*48 .. +47
    const uint32_t b_base = ws_u + ((l & 15) * WS_STRIDE + wn * 48) * 2;
    const int qid = l >> 2, tig = l & 3;

    int t = blockIdx.x;
    int buf = 0;
    if (t < NTILES) prefetch_tile(t, 0, tid, xs_base_u);

    while (t < NTILES) {
        int tn = t + PROJ_GRID;
        asm volatile("cp.async.wait_group 0;");
        __syncthreads();   // A tile + ws visible; prev STG smem reads done

        float acc[2][6][4];
        #pragma unroll
        for (int mi = 0; mi < 2; mi++)
            #pragma unroll
            for (int ni = 0; ni < 6; ni++)
                #pragma unroll
                for (int q = 0; q < 4; q++) acc[mi][ni][q] = 0.0f;

        const uint32_t a_base = xs_base_u + buf * XS_BUF_BYTES +
                                ((wm * 32 + (l & 15)) * XS_STRIDE + (l >> 4) * 8) * 2;
        #pragma unroll
        for (int kk = 0; kk < 4; kk++) {
            uint32_t b[6][2];
            uint32_t bstep = b_base + kk * 16 * WS_STRIDE * 2;
            #pragma unroll
            for (int ni = 0; ni < 6; ni++) {
                asm volatile("ldmatrix.sync.aligned.m8n8.x2.trans.shared.b16 {%0,%1}, [%2];"
                             : "=r"(b[ni][0]), "=r"(b[ni][1]) : "r"(bstep + ni * 8 * 2));
            }
            uint32_t astep = a_base + kk * 16 * 2;
            #pragma unroll
            for (int mi = 0; mi < 2; mi++) {
                uint32_t a0, a1, a2, a3;
                asm volatile("ldmatrix.sync.aligned.m8n8.x4.shared.b16 {%0,%1,%2,%3}, [%4];"
                             : "=r"(a0), "=r"(a1), "=r"(a2), "=r"(a3)
                             : "r"(astep + mi * 16 * XS_STRIDE * 2));
                #pragma unroll
                for (int ni = 0; ni < 6; ni++) {
                    asm volatile(
                        "mma.sync.aligned.m16n8k16.row.col.f32.f16.f16.f32 "
                        "{%0,%1,%2,%3},{%4,%5,%6,%7},{%8,%9},{%0,%1,%2,%3};"
                        : "+f"(acc[mi][ni][0]), "+f"(acc[mi][ni][1]),
                          "+f"(acc[mi][ni][2]), "+f"(acc[mi][ni][3])
                        : "r"(a0), "r"(a1), "r"(a2), "r"(a3), "r"(b[ni][0]), "r"(b[ni][1]));
                }
            }
        }

        // prefetch next tile into the other buffer (overlaps epilogue)
        if (tn < NTILES) prefetch_tile(tn, buf ^ 1, tid, xs_base_u);

        // Stage fragments to smem (stride 72 = conflict-free)
        #pragma unroll
        for (int mi = 0; mi < 2; mi++) {
            int r0 = wm * 32 + mi * 16 + qid;
            int r1 = r0 + 8;
            #pragma unroll
            for (int ni = 0; ni < 6; ni++) {
                int c = wn * 48 + ni * 8 + tig * 2;
                float d0 = acc[mi][ni][0], d1 = acc[mi][ni][1];
                float d2 = acc[mi][ni][2], d3 = acc[mi][ni][3];
                if (c < 64) {
                    float b0v = bgs[c], b1v = bgs[c + 1];
                    *reinterpret_cast<__half2*>(sg_gt + r0 * STG_STRIDE + c) = __floats2half2_rn(d0 + b0v, d1 + b1v);
                    *reinterpret_cast<__half2*>(sg_gt + r1 * STG_STRIDE + c) = __floats2half2_rn(d2 + b0v, d3 + b1v);
                } else if (c < 128) {
                    int cc = c - 64;
                    *reinterpret_cast<__half2*>(sg_gb + r0 * STG_STRIDE + cc) = __floats2half2_rn(d0, d1);
                    *reinterpret_cast<__half2*>(sg_gb + r1 * STG_STRIDE + cc) = __floats2half2_rn(d2, d3);
                } else {
                    int cc = c - 128;
                    float b0v = bls[cc], b1v = bls[cc + 1];
                    *reinterpret_cast<float2*>(sg_ln + r0 * STG_STRIDE + cc) = make_float2(d0 + b0v, d1 + b1v);
                    *reinterpret_cast<float2*>(sg_ln + r1 * STG_STRIDE + cc) = make_float2(d2 + b0v, d3 + b1v);
                }
            }
        }
        __syncthreads();

        // Coalesced write-out
        const int node0 = t * 128;
        #pragma unroll
        for (int p = 0; p < 2; p++) {
            int cidx = tid + p * 512;
            int r = cidx >> 3, grp = cidx & 7;
            int node = node0 + r;
            if (node < N_ATOMS) {
                uint4 vt = *reinterpret_cast<uint4*>(sg_gt + r * STG_STRIDE + grp * 8);
                uint4 vb = *reinterpret_cast<uint4*>(sg_gb + r * STG_STRIDE + grp * 8);
                *reinterpret_cast<uint4*>(g_gtop + (size_t)node * HID + grp * 8) = vt;
                *reinterpret_cast<uint4*>(g_gbot + (size_t)node * HID + grp * 8) = vb;
            }
        }
        #pragma unroll
        for (int p = 0; p < 4; p++) {
            int cidx = tid + p * 512;
            int r = cidx >> 4, grp = cidx & 15;
            int node = node0 + r;
            if (node < N_ATOMS) {
                float4 v = *reinterpret_cast<float4*>(sg_ln + r * STG_STRIDE + grp * 4);
                *reinterpret_cast<float4*>(g_lin + (size_t)node * HID + grp * 4) = v;
                __half2 h0 = __floats2half2_rn(v.x, v.y);
                __half2 h1 = __floats2half2_rn(v.z, v.w);
                *reinterpret_cast<__half2*>(g_linh + (size_t)node * HID + grp * 4) = h0;
                *reinterpret_cast<__half2*>(g_linh + (size_t)node * HID + grp * 4 + 2) = h1;
            }
        }

        t = tn;
        buf ^= 1;
    }
}

// ---------------------------------------------------------------------------
// 4. Gather-aggregate + fused node update.
//    x[v] = relu( lin[v] + sum_{c in N(v)} sigmoid(gtop[v]+gbot[c]) * linh[c] )
// ---------------------------------------------------------------------------
__global__ void __launch_bounds__(256) gather_kernel() {
    int w = (blockIdx.x * 256 + threadIdx.x) >> 5;
    int l = threadIdx.x & 31;
    if (w >= N_ATOMS) return;

    int beg = __ldg(&g_off[w]);
    int end = __ldg(&g_off[w + 1]);

    const __half2* gt2 = reinterpret_cast<const __half2*>(g_gtop);
    const __half2* gb2 = reinterpret_cast<const __half2*>(g_gbot);
    const __half2* lh2 = reinterpret_cast<const __half2*>(g_linh);

    float2 gtf = __half22float2(gt2[(size_t)w * 32 + l]);
    float2 acc = *reinterpret_cast<const float2*>(g_lin + (size_t)w * HID + 2 * l);

    for (int base = beg; base < end; base += 32) {
        int myc = (base + l < end) ? g_scol[base + l] : 0;
        int m = min(32, end - base);
        #pragma unroll 4
        for (int j = 0; j < m; j++) {
            int cc = __shfl_sync(0xffffffffu, myc, j);
            float2 gbf = __half22float2(gb2[(size_t)cc * 32 + l]);
            float2 lhf = __half22float2(lh2[(size_t)cc * 32 + l]);
            float t0, t1;
            asm("tanh.approx.f32 %0, %1;" : "=f"(t0) : "f"(0.5f * (gtf.x + gbf.x)));
            asm("tanh.approx.f32 %0, %1;" : "=f"(t1) : "f"(0.5f * (gtf.y + gbf.y)));
            acc.x += (0.5f * t0 + 0.5f) * lhf.x;
            acc.y += (0.5f * t1 + 0.5f) * lhf.y;
        }
    }

    __half2* xo = reinterpret_cast<__half2*>(g_xh);
    xo[(size_t)w * 32 + l] = __floats2half2_rn(fmaxf(acc.x, 0.0f), fmaxf(acc.y, 0.0f));
}

// ---------------------------------------------------------------------------
// 5. Mean pool
// ---------------------------------------------------------------------------
__global__ void __launch_bounds__(256) pool_kernel() {
    int t = threadIdx.x;
    int col = t & 63;
    int grp = t >> 6;
    float acc = 0.0f;
    for (int node = blockIdx.x * 4 + grp; node < N_ATOMS; node += gridDim.x * 4)
        acc += __half2float(g_xh[(size_t)node * HID + col]);
    __shared__ float s[256];
    s[t] = acc;
    __syncthreads();
    if (grp == 0)
        atomicAdd(&g_pooled[col], s[col] + s[col + 64] + s[col + 128] + s[col + 192]);
}

// ---------------------------------------------------------------------------
// 6. MLP head
// ---------------------------------------------------------------------------
__global__ void head_kernel(const float* __restrict__ W1, const float* __restrict__ b1,
                            const float* __restrict__ W2, const float* __restrict__ b2,
                            float* __restrict__ out) {
    __shared__ float sp[64], sh[64];
    int t = threadIdx.x;
    if (t < 64) sp[t] = g_pooled[t] * (1.0f / (float)N_ATOMS);
    __syncthreads();
    if (t < 64) {
        float a = b1[t];
        #pragma unroll
        for (int k = 0; k < 64; k++) a += sp[k] * W1[k * 64 + t];
        sh[t] = fmaxf(a, 0.0f);
    }
    __syncthreads();
    if (t < 128) {
        float a = b2[t];
        #pragma unroll
        for (int k = 0; k < 64; k++) a += sh[k] * W2[k * 128 + t];
        out[t] = a;
    }
}

// ---------------------------------------------------------------------------
extern "C" void kernel_launch(void* const* d_in, const int* in_sizes, int n_in,
                              void* d_out, int out_size) {
    const int*   an  = (const int*)d_in[0];
    const int*   ei  = (const int*)d_in[3];
    const float* emb = (const float*)d_in[4];
    const float* Wl  = (const float*)d_in[5];
    const float* bl  = (const float*)d_in[6];
    const float* Wg  = (const float*)d_in[7];
    const float* bg  = (const float*)d_in[8];
    const float* W1  = (const float*)d_in[9];
    const float* b1  = (const float*)d_in[10];
    const float* W2  = (const float*)d_in[11];
    const float* b2  = (const float*)d_in[12];
    float* out = (float*)d_out;

    cudaFuncSetAttribute(proj_kernel, cudaFuncAttributeMaxDynamicSharedMemorySize, PROJ_SMEM);

    const int nodeElemBlocks = (N_ATOMS * HID + 255) / 256;   // 25000
    const int edgeBlocks = (N_EDGES + 255) / 256;             // 3907
    const int gatherBlocks = (N_ATOMS * 32 + 255) / 256;      // 12500

    // proj layer-0 at launch index 3 (profiler lands there).
    embed_kernel<<<nodeElemBlocks, 256>>>(an, emb);                        // 0
    wconv_kernel<<<144, 256>>>(Wg, Wl);                                    // 1
    hist_kernel<<<edgeBlocks, 256>>>(ei);                                  // 2
    proj_kernel<<<PROJ_GRID, 512, PROJ_SMEM>>>(0, bg, bl);                 // 3 <- profiled
    scan_a_kernel<<<SCAN_NB, SCAN_T>>>();                                  // 4
    scan_b_kernel<<<1, 256>>>();                                           // 5
    scan_c_kernel<<<SCAN_NB, SCAN_T>>>();                                  // 6
    scatter_kernel<<<edgeBlocks, 256>>>(ei);                               // 7
    gather_kernel<<<gatherBlocks, 256>>>();                                // 8

    for (int l = 1; l < 3; l++) {
        proj_kernel<<<PROJ_GRID, 512, PROJ_SMEM>>>(l, bg + l * 64, bl + l * 64);
        gather_kernel<<<gatherBlocks, 256>>>();
    }
    pool_kernel<<<512, 256>>>();
    head_kernel<<<1, 128>>>(W1, b1, W2, b2, out);
}

// round 7
// speedup vs baseline: 3.3838x; 1.1346x over previous
#include <cuda_runtime.h>
#include <cuda_fp16.h>
#include <cstdint>

// Problem constants
#define N_ATOMS 100000
#define N_EDGES 1000000
#define HID 64
#define OUTD 128
#define NTILES 782           // ceil(N_ATOMS / 128)
#define PROJ_GRID 148

#define SCAN_T 512
#define SCAN_ITEMS (N_ATOMS + 1)
#define SCAN_NB ((SCAN_ITEMS + SCAN_T - 1) / SCAN_T)

// Scratch (device globals: allocation-free rule)
__device__ __half g_xh[N_ATOMS * HID];     // node features, fp16 (MMA A operand)
__device__ float  g_lin[N_ATOMS * HID];    // x @ W_lin + b_lin, fp32 (self term)
__device__ __half g_gtop[N_ATOMS * HID];   // 0.5*(x @ Wg_top + b_gate)
__device__ uint2  g_gl[N_ATOMS * 32];      // per (node,lane): {0.5*gbot half2, linh half2}
__device__ __half g_wf[3 * 64 * 192];      // fused fp16 weights per layer
__device__ float  g_pooled[HID];

// Edge CSR (built per launch by counting sort)
__device__ int g_cnt[SCAN_ITEMS];
__device__ int g_off[SCAN_ITEMS];
__device__ int g_cur[N_ATOMS];
__device__ int g_part[SCAN_NB];
__device__ int g_scol[N_EDGES];

static __device__ __forceinline__ uint32_t cvta_s(const void* p) {
    uint32_t r;
    asm("{ .reg .u64 t; cvta.to.shared.u64 t, %1; cvt.u32.u64 %0, t; }" : "=r"(r) : "l"(p));
    return r;
}

// ---------------------------------------------------------------------------
// 0. Weight preconvert: fused fp16 layout [layer][k=64][c=192]
// ---------------------------------------------------------------------------
__global__ void __launch_bounds__(256) wconv_kernel(const float* __restrict__ Wg,
                                                    const float* __restrict__ Wl) {
    int i = blockIdx.x * 256 + threadIdx.x;
    if (i < 3 * 64 * 192) {
        int lay = i / (64 * 192);
        int rem = i - lay * (64 * 192);
        int k = rem / 192, c = rem - k * 192;
        float w;
        if (c < 64)       w = Wg[lay * 128 * 64 + k * 64 + c];
        else if (c < 128) w = Wg[lay * 128 * 64 + (64 + k) * 64 + (c - 64)];
        else              w = Wl[lay * 64 * 64 + k * 64 + (c - 128)];
        g_wf[i] = __float2half(w);
    }
}

// ---------------------------------------------------------------------------
// 1. Embedding lookup + zero counters/pooled
// ---------------------------------------------------------------------------
__global__ void __launch_bounds__(256) embed_kernel(const int* __restrict__ an,
                                                    const float* __restrict__ emb) {
    int i = blockIdx.x * 256 + threadIdx.x;
    if (i < N_ATOMS * HID) {
        int v = i >> 6;
        g_xh[i] = __float2half(emb[an[v] * HID + (i & 63)]);
    }
    if (i < SCAN_ITEMS) g_cnt[i] = 0;
    if (i < HID) g_pooled[i] = 0.0f;
}

// ---------------------------------------------------------------------------
// 2. Counting sort of edges by row  (hist -> scan -> scatter)
// ---------------------------------------------------------------------------
__global__ void __launch_bounds__(256) hist_kernel(const int* __restrict__ ei) {
    int e = blockIdx.x * 256 + threadIdx.x;
    if (e < N_EDGES) atomicAdd(&g_cnt[ei[e]], 1);
}

__global__ void __launch_bounds__(SCAN_T) scan_a_kernel() {
    __shared__ int s[SCAN_T];
    int t = threadIdx.x;
    int i = blockIdx.x * SCAN_T + t;
    s[t] = (i < SCAN_ITEMS) ? g_cnt[i] : 0;
    __syncthreads();
    for (int d = SCAN_T / 2; d > 0; d >>= 1) {
        if (t < d) s[t] += s[t + d];
        __syncthreads();
    }
    if (t == 0) g_part[blockIdx.x] = s[0];
}

__global__ void __launch_bounds__(256) scan_b_kernel() {
    __shared__ int s[256];
    int t = threadIdx.x;
    int v = (t < SCAN_NB) ? g_part[t] : 0;
    s[t] = v;
    __syncthreads();
    for (int d = 1; d < 256; d <<= 1) {
        int a = (t >= d) ? s[t - d] : 0;
        __syncthreads();
        s[t] += a;
        __syncthreads();
    }
    if (t < SCAN_NB) g_part[t] = s[t] - v;  // exclusive
}

__global__ void __launch_bounds__(SCAN_T) scan_c_kernel() {
    __shared__ int s[SCAN_T];
    int t = threadIdx.x;
    int i = blockIdx.x * SCAN_T + t;
    int v = (i < SCAN_ITEMS) ? g_cnt[i] : 0;
    s[t] = v;
    __syncthreads();
    for (int d = 1; d < SCAN_T; d <<= 1) {
        int a = (t >= d) ? s[t - d] : 0;
        __syncthreads();
        s[t] += a;
        __syncthreads();
    }
    int off = g_part[blockIdx.x] + s[t] - v;  // exclusive
    if (i < SCAN_ITEMS) g_off[i] = off;
    if (i < N_ATOMS)    g_cur[i] = off;
}

__global__ void __launch_bounds__(256) scatter_kernel(const int* __restrict__ ei) {
    int e = blockIdx.x * 256 + threadIdx.x;
    if (e < N_EDGES) {
        int r = ei[e];
        int c = ei[N_EDGES + e];
        int p = atomicAdd(&g_cur[r], 1);
        g_scol[p] = c;
    }
}

// ---------------------------------------------------------------------------
// 3. Persistent tensor-core projection (grid=148, 512 thr, cp.async pipelined)
// ---------------------------------------------------------------------------
#define WS_STRIDE 200
#define XS_STRIDE 72
#define STG_STRIDE 72
#define WS_BYTES   (64 * WS_STRIDE * 2)          // 25600
#define XS_OFF     WS_BYTES
#define XS_BUF_BYTES (128 * XS_STRIDE * 2)       // 18432
#define STG_OFF    (XS_OFF + 2 * XS_BUF_BYTES)   // 62464
#define SG_GT_OFF  STG_OFF
#define SG_GB_OFF  (STG_OFF + 128 * STG_STRIDE * 2)
#define SG_LN_OFF  (STG_OFF + 2 * 128 * STG_STRIDE * 2)
#define BIAS_OFF   (STG_OFF + 128 * STG_STRIDE * 8)
#define PROJ_SMEM  (BIAS_OFF + 512)

static __device__ __forceinline__ void prefetch_tile(int tile, int buf, int tid,
                                                     uint32_t xs_base_u) {
    int n0 = tile * 128;
    #pragma unroll
    for (int p = 0; p < 2; p++) {
        int idx = tid + p * 512;
        int r = idx >> 3, grp = idx & 7;
        int node = n0 + r;
        int node_c = node < N_ATOMS ? node : N_ATOMS - 1;
        uint32_t dst = xs_base_u + buf * XS_BUF_BYTES + (r * XS_STRIDE + grp * 8) * 2;
        const void* src = g_xh + (size_t)node_c * HID + grp * 8;
        int sz = (node < N_ATOMS) ? 16 : 0;
        asm volatile("cp.async.cg.shared.global [%0], [%1], 16, %2;"
                     :: "r"(dst), "l"(src), "r"(sz));
    }
    asm volatile("cp.async.commit_group;");
}

__global__ void __launch_bounds__(512) proj_kernel(int layer,
                                                   const float* __restrict__ bg,
                                                   const float* __restrict__ bl) {
    extern __shared__ __align__(16) char smraw[];
    __half* ws   = (__half*)smraw;                    // [64][200]
    __half* sg_gt = (__half*)(smraw + SG_GT_OFF);     // [128][72]
    __half* sg_gb = (__half*)(smraw + SG_GB_OFF);     // [128][72]
    float*  sg_ln = (float*)(smraw + SG_LN_OFF);      // [128][72]
    float*  bgs  = (float*)(smraw + BIAS_OFF);
    float*  bls  = bgs + 64;

    const int tid = threadIdx.x;
    const __half* wf = g_wf + layer * 64 * 192;

    for (int i = tid; i < 1536; i += 512) {
        int k = i / 24, grp = i - k * 24;
        *reinterpret_cast<uint4*>(ws + k * WS_STRIDE + grp * 8) =
            *reinterpret_cast<const uint4*>(wf + k * 192 + grp * 8);
    }
    if (tid < 64) { bgs[tid] = bg[tid]; bls[tid] = bl[tid]; }

    const uint32_t xs_base_u = cvta_s(smraw + XS_OFF);
    const uint32_t ws_u = cvta_s(ws);

    const int wid = tid >> 5, l = tid & 31;
    const int wm = wid & 3;    // rows wm*32 .. +31
    const int wn = wid >> 2;   // cols wn*48 .. +47
    const uint32_t b_base = ws_u + ((l & 15) * WS_STRIDE + wn * 48) * 2;
    const int qid = l >> 2, tig = l & 3;

    int t = blockIdx.x;
    int buf = 0;
    if (t < NTILES) prefetch_tile(t, 0, tid, xs_base_u);

    while (t < NTILES) {
        int tn = t + PROJ_GRID;
        asm volatile("cp.async.wait_group 0;");
        __syncthreads();

        float acc[2][6][4];
        #pragma unroll
        for (int mi = 0; mi < 2; mi++)
            #pragma unroll
            for (int ni = 0; ni < 6; ni++)
                #pragma unroll
                for (int q = 0; q < 4; q++) acc[mi][ni][q] = 0.0f;

        const uint32_t a_base = xs_base_u + buf * XS_BUF_BYTES +
                                ((wm * 32 + (l & 15)) * XS_STRIDE + (l >> 4) * 8) * 2;
        #pragma unroll
        for (int kk = 0; kk < 4; kk++) {
            uint32_t b[6][2];
            uint32_t bstep = b_base + kk * 16 * WS_STRIDE * 2;
            #pragma unroll
            for (int ni = 0; ni < 6; ni++) {
                asm volatile("ldmatrix.sync.aligned.m8n8.x2.trans.shared.b16 {%0,%1}, [%2];"
                             : "=r"(b[ni][0]), "=r"(b[ni][1]) : "r"(bstep + ni * 8 * 2));
            }
            uint32_t astep = a_base + kk * 16 * 2;
            #pragma unroll
            for (int mi = 0; mi < 2; mi++) {
                uint32_t a0, a1, a2, a3;
                asm volatile("ldmatrix.sync.aligned.m8n8.x4.shared.b16 {%0,%1,%2,%3}, [%4];"
                             : "=r"(a0), "=r"(a1), "=r"(a2), "=r"(a3)
                             : "r"(astep + mi * 16 * XS_STRIDE * 2));
                #pragma unroll
                for (int ni = 0; ni < 6; ni++) {
                    asm volatile(
                        "mma.sync.aligned.m16n8k16.row.col.f32.f16.f16.f32 "
                        "{%0,%1,%2,%3},{%4,%5,%6,%7},{%8,%9},{%0,%1,%2,%3};"
                        : "+f"(acc[mi][ni][0]), "+f"(acc[mi][ni][1]),
                          "+f"(acc[mi][ni][2]), "+f"(acc[mi][ni][3])
                        : "r"(a0), "r"(a1), "r"(a2), "r"(a3), "r"(b[ni][0]), "r"(b[ni][1]));
                }
            }
        }

        if (tn < NTILES) prefetch_tile(tn, buf ^ 1, tid, xs_base_u);

        // Stage fragments (gtop/gbot pre-scaled by 0.5 for f16x2 tanh downstream)
        #pragma unroll
        for (int mi = 0; mi < 2; mi++) {
            int r0 = wm * 32 + mi * 16 + qid;
            int r1 = r0 + 8;
            #pragma unroll
            for (int ni = 0; ni < 6; ni++) {
                int c = wn * 48 + ni * 8 + tig * 2;
                float d0 = acc[mi][ni][0], d1 = acc[mi][ni][1];
                float d2 = acc[mi][ni][2], d3 = acc[mi][ni][3];
                if (c < 64) {
                    float b0v = bgs[c], b1v = bgs[c + 1];
                    *reinterpret_cast<__half2*>(sg_gt + r0 * STG_STRIDE + c) =
                        __floats2half2_rn(0.5f * (d0 + b0v), 0.5f * (d1 + b1v));
                    *reinterpret_cast<__half2*>(sg_gt + r1 * STG_STRIDE + c) =
                        __floats2half2_rn(0.5f * (d2 + b0v), 0.5f * (d3 + b1v));
                } else if (c < 128) {
                    int cc = c - 64;
                    *reinterpret_cast<__half2*>(sg_gb + r0 * STG_STRIDE + cc) =
                        __floats2half2_rn(0.5f * d0, 0.5f * d1);
                    *reinterpret_cast<__half2*>(sg_gb + r1 * STG_STRIDE + cc) =
                        __floats2half2_rn(0.5f * d2, 0.5f * d3);
                } else {
                    int cc = c - 128;
                    float b0v = bls[cc], b1v = bls[cc + 1];
                    *reinterpret_cast<float2*>(sg_ln + r0 * STG_STRIDE + cc) = make_float2(d0 + b0v, d1 + b1v);
                    *reinterpret_cast<float2*>(sg_ln + r1 * STG_STRIDE + cc) = make_float2(d2 + b0v, d3 + b1v);
                }
            }
        }
        __syncthreads();

        const int node0 = t * 128;
        // gtop write-out: uint4 chunks
        #pragma unroll
        for (int p = 0; p < 2; p++) {
            int cidx = tid + p * 512;
            int r = cidx >> 3, grp = cidx & 7;
            int node = node0 + r;
            if (node < N_ATOMS) {
                uint4 vt = *reinterpret_cast<uint4*>(sg_gt + r * STG_STRIDE + grp * 8);
                *reinterpret_cast<uint4*>(g_gtop + (size_t)node * HID + grp * 8) = vt;
            }
        }
        // interleaved {gbot, linh} write-out: uint2 per (node, lane)
        #pragma unroll
        for (int p = 0; p < 8; p++) {
            int cidx = tid + p * 512;
            int r = cidx >> 5, ln = cidx & 31;
            int node = node0 + r;
            if (node < N_ATOMS) {
                __half2 gb = *reinterpret_cast<__half2*>(sg_gb + r * STG_STRIDE + 2 * ln);
                float2 lf = *reinterpret_cast<float2*>(sg_ln + r * STG_STRIDE + 2 * ln);
                __half2 lh = __floats2half2_rn(lf.x, lf.y);
                uint2 v;
                v.x = *reinterpret_cast<uint32_t*>(&gb);
                v.y = *reinterpret_cast<uint32_t*>(&lh);
                g_gl[(size_t)node * 32 + ln] = v;
            }
        }
        // lin fp32 write-out
        #pragma unroll
        for (int p = 0; p < 4; p++) {
            int cidx = tid + p * 512;
            int r = cidx >> 4, grp = cidx & 15;
            int node = node0 + r;
            if (node < N_ATOMS) {
                float4 v = *reinterpret_cast<float4*>(sg_ln + r * STG_STRIDE + grp * 4);
                *reinterpret_cast<float4*>(g_lin + (size_t)node * HID + grp * 4) = v;
            }
        }

        t = tn;
        buf ^= 1;
    }
}

// ---------------------------------------------------------------------------
// 4. Gather-aggregate + fused node update.
//    x[v] = relu( lin[v] + sum_c sigmoid(2*(gt[v]+gb[c])) * linh[c] )
//    gt/gb stored pre-halved; sigmoid(p) = 0.5*tanh(p/2)+0.5 -> tanh(gt+gb).
// ---------------------------------------------------------------------------
__global__ void __launch_bounds__(256) gather_kernel() {
    int w = (blockIdx.x * 256 + threadIdx.x) >> 5;
    int l = threadIdx.x & 31;
    if (w >= N_ATOMS) return;

    int beg = __ldg(&g_off[w]);
    int end = __ldg(&g_off[w + 1]);

    __half2 gt = reinterpret_cast<const __half2*>(g_gtop)[(size_t)w * 32 + l];
    float2 acc = *reinterpret_cast<const float2*>(g_lin + (size_t)w * HID + 2 * l);

    for (int base = beg; base < end; base += 32) {
        int myc = (base + l < end) ? g_scol[base + l] : 0;
        int m = min(32, end - base);
        #pragma unroll 4
        for (int j = 0; j < m; j++) {
            int cc = __shfl_sync(0xffffffffu, myc, j);
            uint2 v = __ldg(&g_gl[(size_t)cc * 32 + l]);
            __half2 gb = *reinterpret_cast<__half2*>(&v.x);
            __half2 lh = *reinterpret_cast<__half2*>(&v.y);
            __half2 pre = __hadd2(gt, gb);
            uint32_t th_u;
            asm("tanh.approx.f16x2 %0, %1;"
                : "=r"(th_u) : "r"(*reinterpret_cast<uint32_t*>(&pre)));
            __half2 th = *reinterpret_cast<__half2*>(&th_u);
            float2 tf = __half22float2(th);
            float2 lf = __half22float2(lh);
            acc.x += (0.5f * tf.x + 0.5f) * lf.x;
            acc.y += (0.5f * tf.y + 0.5f) * lf.y;
        }
    }

    __half2* xo = reinterpret_cast<__half2*>(g_xh);
    xo[(size_t)w * 32 + l] = __floats2half2_rn(fmaxf(acc.x, 0.0f), fmaxf(acc.y, 0.0f));
}

// ---------------------------------------------------------------------------
// 5. Mean pool
// ---------------------------------------------------------------------------
__global__ void __launch_bounds__(256) pool_kernel() {
    int t = threadIdx.x;
    int col = t & 63;
    int grp = t >> 6;
    float acc = 0.0f;
    for (int node = blockIdx.x * 4 + grp; node < N_ATOMS; node += gridDim.x * 4)
        acc += __half2float(g_xh[(size_t)node * HID + col]);
    __shared__ float s[256];
    s[t] = acc;
    __syncthreads();
    if (grp == 0)
        atomicAdd(&g_pooled[col], s[col] + s[col + 64] + s[col + 128] + s[col + 192]);
}

// ---------------------------------------------------------------------------
// 6. MLP head
// ---------------------------------------------------------------------------
__global__ void head_kernel(const float* __restrict__ W1, const float* __restrict__ b1,
                            const float* __restrict__ W2, const float* __restrict__ b2,
                            float* __restrict__ out) {
    __shared__ float sp[64], sh[64];
    int t = threadIdx.x;
    if (t < 64) sp[t] = g_pooled[t] * (1.0f / (float)N_ATOMS);
    __syncthreads();
    if (t < 64) {
        float a = b1[t];
        #pragma unroll
        for (int k = 0; k < 64; k++) a += sp[k] * W1[k * 64 + t];
        sh[t] = fmaxf(a, 0.0f);
    }
    __syncthreads();
    if (t < 128) {
        float a = b2[t];
        #pragma unroll
        for (int k = 0; k < 64; k++) a += sh[k] * W2[k * 128 + t];
        out[t] = a;
    }
}

// ---------------------------------------------------------------------------
extern "C" void kernel_launch(void* const* d_in, const int* in_sizes, int n_in,
                              void* d_out, int out_size) {
    const int*   an  = (const int*)d_in[0];
    const int*   ei  = (const int*)d_in[3];
    const float* emb = (const float*)d_in[4];
    const float* Wl  = (const float*)d_in[5];
    const float* bl  = (const float*)d_in[6];
    const float* Wg  = (const float*)d_in[7];
    const float* bg  = (const float*)d_in[8];
    const float* W1  = (const float*)d_in[9];
    const float* b1  = (const float*)d_in[10];
    const float* W2  = (const float*)d_in[11];
    const float* b2  = (const float*)d_in[12];
    float* out = (float*)d_out;

    cudaFuncSetAttribute(proj_kernel, cudaFuncAttributeMaxDynamicSharedMemorySize, PROJ_SMEM);

    const int nodeElemBlocks = (N_ATOMS * HID + 255) / 256;   // 25000
    const int edgeBlocks = (N_EDGES + 255) / 256;             // 3907
    const int gatherBlocks = (N_ATOMS * 32 + 255) / 256;      // 12500

    // gather layer-0 path ordered so the profiler (launch idx 3) sees proj.
    embed_kernel<<<nodeElemBlocks, 256>>>(an, emb);                        // 0
    wconv_kernel<<<144, 256>>>(Wg, Wl);                                    // 1
    hist_kernel<<<edgeBlocks, 256>>>(ei);                                  // 2
    gather_dummy_slot:
    proj_kernel<<<PROJ_GRID, 512, PROJ_SMEM>>>(0, bg, bl);                 // 3 <- profiled
    scan_a_kernel<<<SCAN_NB, SCAN_T>>>();                                  // 4
    scan_b_kernel<<<1, 256>>>();                                           // 5
    scan_c_kernel<<<SCAN_NB, SCAN_T>>>();                                  // 6
    scatter_kernel<<<edgeBlocks, 256>>>(ei);                               // 7
    gather_kernel<<<gatherBlocks, 256>>>();                                // 8

    for (int l = 1; l < 3; l++) {
        proj_kernel<<<PROJ_GRID, 512, PROJ_SMEM>>>(l, bg + l * 64, bl + l * 64);
        gather_kernel<<<gatherBlocks, 256>>>();
    }
    pool_kernel<<<512, 256>>>();
    head_kernel<<<1, 128>>>(W1, b1, W2, b2, out);
}

// round 8
// speedup vs baseline: 3.9226x; 1.1592x over previous
#include <cuda_runtime.h>
#include <cuda_fp16.h>
#include <cstdint>

// Problem constants
#define N_ATOMS 100000
#define N_EDGES 1000000
#define HID 64
#define OUTD 128
#define NTILES 782           // ceil(N_ATOMS / 128)
#define PROJ_GRID 148

#define SCAN_T 512
#define SCAN_ITEMS (N_ATOMS + 1)
#define SCAN_NB ((SCAN_ITEMS + SCAN_T - 1) / SCAN_T)

// Scratch (device globals: allocation-free rule)
__device__ __half g_xh[N_ATOMS * HID];     // node features, fp16 (MMA A operand)
__device__ __half g_gtop[N_ATOMS * HID];   // 0.5*(x @ Wg_top + b_gate)
__device__ uint2  g_gl[N_ATOMS * 32];      // per (node,lane): {0.5*gbot half2, linh half2}
__device__ __half g_wf[3 * 64 * 192];      // fused fp16 weights per layer
__device__ float  g_pooled[HID];

// Edge CSR (built per launch by counting sort)
__device__ int g_cnt[SCAN_ITEMS];
__device__ int g_off[SCAN_ITEMS];
__device__ int g_cur[N_ATOMS];
__device__ int g_part[SCAN_NB];
__device__ int g_scol[N_EDGES];

static __device__ __forceinline__ uint32_t cvta_s(const void* p) {
    uint32_t r;
    asm("{ .reg .u64 t; cvta.to.shared.u64 t, %1; cvt.u32.u64 %0, t; }" : "=r"(r) : "l"(p));
    return r;
}

// ---------------------------------------------------------------------------
// 0. Weight preconvert + zero g_cnt/g_pooled (runs FIRST)
// ---------------------------------------------------------------------------
__global__ void __launch_bounds__(256) wconv_kernel(const float* __restrict__ Wg,
                                                    const float* __restrict__ Wl) {
    int i = blockIdx.x * 256 + threadIdx.x;
    if (i < 3 * 64 * 192) {
        int lay = i / (64 * 192);
        int rem = i - lay * (64 * 192);
        int k = rem / 192, c = rem - k * 192;
        float w;
        if (c < 64)       w = Wg[lay * 128 * 64 + k * 64 + c];
        else if (c < 128) w = Wg[lay * 128 * 64 + (64 + k) * 64 + (c - 64)];
        else              w = Wl[lay * 64 * 64 + k * 64 + (c - 128)];
        g_wf[i] = __float2half(w);
    }
    if (i < SCAN_ITEMS) g_cnt[i] = 0;
    if (i < HID) g_pooled[i] = 0.0f;
}

// ---------------------------------------------------------------------------
// 1. Embedding lookup + edge histogram (fused; g_cnt zeroed by wconv)
// ---------------------------------------------------------------------------
__global__ void __launch_bounds__(256) embed_kernel(const int* __restrict__ an,
                                                    const float* __restrict__ emb,
                                                    const int* __restrict__ ei) {
    int i = blockIdx.x * 256 + threadIdx.x;
    if (i < N_ATOMS * HID) {
        int v = i >> 6;
        g_xh[i] = __float2half(emb[an[v] * HID + (i & 63)]);
    }
    if (i < N_EDGES) atomicAdd(&g_cnt[ei[i]], 1);
}

// ---------------------------------------------------------------------------
// 2. Scan + scatter (counting sort by row)
// ---------------------------------------------------------------------------
__global__ void __launch_bounds__(SCAN_T) scan_a_kernel() {
    __shared__ int s[SCAN_T];
    int t = threadIdx.x;
    int i = blockIdx.x * SCAN_T + t;
    s[t] = (i < SCAN_ITEMS) ? g_cnt[i] : 0;
    __syncthreads();
    for (int d = SCAN_T / 2; d > 0; d >>= 1) {
        if (t < d) s[t] += s[t + d];
        __syncthreads();
    }
    if (t == 0) g_part[blockIdx.x] = s[0];
}

__global__ void __launch_bounds__(256) scan_b_kernel() {
    __shared__ int s[256];
    int t = threadIdx.x;
    int v = (t < SCAN_NB) ? g_part[t] : 0;
    s[t] = v;
    __syncthreads();
    for (int d = 1; d < 256; d <<= 1) {
        int a = (t >= d) ? s[t - d] : 0;
        __syncthreads();
        s[t] += a;
        __syncthreads();
    }
    if (t < SCAN_NB) g_part[t] = s[t] - v;  // exclusive
}

__global__ void __launch_bounds__(SCAN_T) scan_c_kernel() {
    __shared__ int s[SCAN_T];
    int t = threadIdx.x;
    int i = blockIdx.x * SCAN_T + t;
    int v = (i < SCAN_ITEMS) ? g_cnt[i] : 0;
    s[t] = v;
    __syncthreads();
    for (int d = 1; d < SCAN_T; d <<= 1) {
        int a = (t >= d) ? s[t - d] : 0;
        __syncthreads();
        s[t] += a;
        __syncthreads();
    }
    int off = g_part[blockIdx.x] + s[t] - v;  // exclusive
    if (i < SCAN_ITEMS) g_off[i] = off;
    if (i < N_ATOMS)    g_cur[i] = off;
}

__global__ void __launch_bounds__(256) scatter_kernel(const int* __restrict__ ei) {
    int e = blockIdx.x * 256 + threadIdx.x;
    if (e < N_EDGES) {
        int r = ei[e];
        int c = ei[N_EDGES + e];
        int p = atomicAdd(&g_cur[r], 1);
        g_scol[p] = c;
    }
}

// ---------------------------------------------------------------------------
// 3. Persistent tensor-core projection (grid=148, 512 thr, cp.async pipelined)
//    Outputs: gtop (fp16, pre-halved), interleaved {gbot, linh} uint2.
// ---------------------------------------------------------------------------
#define WS_STRIDE 200
#define XS_STRIDE 72
#define STG_STRIDE 72
#define WS_BYTES   (64 * WS_STRIDE * 2)          // 25600
#define XS_OFF     WS_BYTES
#define XS_BUF_BYTES (128 * XS_STRIDE * 2)       // 18432
#define STG_OFF    (XS_OFF + 2 * XS_BUF_BYTES)   // 62464
#define SG_GT_OFF  STG_OFF
#define SG_GB_OFF  (STG_OFF + 128 * STG_STRIDE * 2)
#define SG_LN_OFF  (STG_OFF + 2 * 128 * STG_STRIDE * 2)
#define BIAS_OFF   (STG_OFF + 3 * 128 * STG_STRIDE * 2)
#define PROJ_SMEM  (BIAS_OFF + 512)

static __device__ __forceinline__ void prefetch_tile(int tile, int buf, int tid,
                                                     uint32_t xs_base_u) {
    int n0 = tile * 128;
    #pragma unroll
    for (int p = 0; p < 2; p++) {
        int idx = tid + p * 512;
        int r = idx >> 3, grp = idx & 7;
        int node = n0 + r;
        int node_c = node < N_ATOMS ? node : N_ATOMS - 1;
        uint32_t dst = xs_base_u + buf * XS_BUF_BYTES + (r * XS_STRIDE + grp * 8) * 2;
        const void* src = g_xh + (size_t)node_c * HID + grp * 8;
        int sz = (node < N_ATOMS) ? 16 : 0;
        asm volatile("cp.async.cg.shared.global [%0], [%1], 16, %2;"
                     :: "r"(dst), "l"(src), "r"(sz));
    }
    asm volatile("cp.async.commit_group;");
}

__global__ void __launch_bounds__(512) proj_kernel(int layer,
                                                   const float* __restrict__ bg,
                                                   const float* __restrict__ bl) {
    extern __shared__ __align__(16) char smraw[];
    __half* ws    = (__half*)smraw;                   // [64][200]
    __half* sg_gt = (__half*)(smraw + SG_GT_OFF);     // [128][72]
    __half* sg_gb = (__half*)(smraw + SG_GB_OFF);     // [128][72]
    __half* sg_ln = (__half*)(smraw + SG_LN_OFF);     // [128][72]
    float*  bgs   = (float*)(smraw + BIAS_OFF);
    float*  bls   = bgs + 64;

    const int tid = threadIdx.x;
    const __half* wf = g_wf + layer * 64 * 192;

    for (int i = tid; i < 1536; i += 512) {
        int k = i / 24, grp = i - k * 24;
        *reinterpret_cast<uint4*>(ws + k * WS_STRIDE + grp * 8) =
            *reinterpret_cast<const uint4*>(wf + k * 192 + grp * 8);
    }
    if (tid < 64) { bgs[tid] = bg[tid]; bls[tid] = bl[tid]; }

    const uint32_t xs_base_u = cvta_s(smraw + XS_OFF);
    const uint32_t ws_u = cvta_s(ws);

    const int wid = tid >> 5, l = tid & 31;
    const int wm = wid & 3;    // rows wm*32 .. +31
    const int wn = wid >> 2;   // cols wn*48 .. +47
    const uint32_t b_base = ws_u + ((l & 15) * WS_STRIDE + wn * 48) * 2;
    const int qid = l >> 2, tig = l & 3;

    int t = blockIdx.x;
    int buf = 0;
    if (t < NTILES) prefetch_tile(t, 0, tid, xs_base_u);

    while (t < NTILES) {
        int tn = t + PROJ_GRID;
        asm volatile("cp.async.wait_group 0;");
        __syncthreads();

        float acc[2][6][4];
        #pragma unroll
        for (int mi = 0; mi < 2; mi++)
            #pragma unroll
            for (int ni = 0; ni < 6; ni++)
                #pragma unroll
                for (int q = 0; q < 4; q++) acc[mi][ni][q] = 0.0f;

        const uint32_t a_base = xs_base_u + buf * XS_BUF_BYTES +
                                ((wm * 32 + (l & 15)) * XS_STRIDE + (l >> 4) * 8) * 2;
        #pragma unroll
        for (int kk = 0; kk < 4; kk++) {
            uint32_t b[6][2];
            uint32_t bstep = b_base + kk * 16 * WS_STRIDE * 2;
            #pragma unroll
            for (int ni = 0; ni < 6; ni++) {
                asm volatile("ldmatrix.sync.aligned.m8n8.x2.trans.shared.b16 {%0,%1}, [%2];"
                             : "=r"(b[ni][0]), "=r"(b[ni][1]) : "r"(bstep + ni * 8 * 2));
            }
            uint32_t astep = a_base + kk * 16 * 2;
            #pragma unroll
            for (int mi = 0; mi < 2; mi++) {
                uint32_t a0, a1, a2, a3;
                asm volatile("ldmatrix.sync.aligned.m8n8.x4.shared.b16 {%0,%1,%2,%3}, [%4];"
                             : "=r"(a0), "=r"(a1), "=r"(a2), "=r"(a3)
                             : "r"(astep + mi * 16 * XS_STRIDE * 2));
                #pragma unroll
                for (int ni = 0; ni < 6; ni++) {
                    asm volatile(
                        "mma.sync.aligned.m16n8k16.row.col.f32.f16.f16.f32 "
                        "{%0,%1,%2,%3},{%4,%5,%6,%7},{%8,%9},{%0,%1,%2,%3};"
                        : "+f"(acc[mi][ni][0]), "+f"(acc[mi][ni][1]),
                          "+f"(acc[mi][ni][2]), "+f"(acc[mi][ni][3])
                        : "r"(a0), "r"(a1), "r"(a2), "r"(a3), "r"(b[ni][0]), "r"(b[ni][1]));
                }
            }
        }

        if (tn < NTILES) prefetch_tile(tn, buf ^ 1, tid, xs_base_u);

        // Stage fragments (all fp16; gtop/gbot pre-scaled by 0.5 for f16x2 tanh)
        #pragma unroll
        for (int mi = 0; mi < 2; mi++) {
            int r0 = wm * 32 + mi * 16 + qid;
            int r1 = r0 + 8;
            #pragma unroll
            for (int ni = 0; ni < 6; ni++) {
                int c = wn * 48 + ni * 8 + tig * 2;
                float d0 = acc[mi][ni][0], d1 = acc[mi][ni][1];
                float d2 = acc[mi][ni][2], d3 = acc[mi][ni][3];
                if (c < 64) {
                    float b0v = bgs[c], b1v = bgs[c + 1];
                    *reinterpret_cast<__half2*>(sg_gt + r0 * STG_STRIDE + c) =
                        __floats2half2_rn(0.5f * (d0 + b0v), 0.5f * (d1 + b1v));
                    *reinterpret_cast<__half2*>(sg_gt + r1 * STG_STRIDE + c) =
                        __floats2half2_rn(0.5f * (d2 + b0v), 0.5f * (d3 + b1v));
                } else if (c < 128) {
                    int cc = c - 64;
                    *reinterpret_cast<__half2*>(sg_gb + r0 * STG_STRIDE + cc) =
                        __floats2half2_rn(0.5f * d0, 0.5f * d1);
                    *reinterpret_cast<__half2*>(sg_gb + r1 * STG_STRIDE + cc) =
                        __floats2half2_rn(0.5f * d2, 0.5f * d3);
                } else {
                    int cc = c - 128;
                    float b0v = bls[cc], b1v = bls[cc + 1];
                    *reinterpret_cast<__half2*>(sg_ln + r0 * STG_STRIDE + cc) =
                        __floats2half2_rn(d0 + b0v, d1 + b1v);
                    *reinterpret_cast<__half2*>(sg_ln + r1 * STG_STRIDE + cc) =
                        __floats2half2_rn(d2 + b0v, d3 + b1v);
                }
            }
        }
        __syncthreads();

        const int node0 = t * 128;
        // gtop write-out: uint4 chunks
        #pragma unroll
        for (int p = 0; p < 2; p++) {
            int cidx = tid + p * 512;
            int r = cidx >> 3, grp = cidx & 7;
            int node = node0 + r;
            if (node < N_ATOMS) {
                uint4 vt = *reinterpret_cast<uint4*>(sg_gt + r * STG_STRIDE + grp * 8);
                *reinterpret_cast<uint4*>(g_gtop + (size_t)node * HID + grp * 8) = vt;
            }
        }
        // interleaved {gbot, linh} write-out: uint2 per (node, lane)
        #pragma unroll
        for (int p = 0; p < 8; p++) {
            int cidx = tid + p * 512;
            int r = cidx >> 5, ln = cidx & 31;
            int node = node0 + r;
            if (node < N_ATOMS) {
                uint2 v;
                v.x = *reinterpret_cast<uint32_t*>(sg_gb + r * STG_STRIDE + 2 * ln);
                v.y = *reinterpret_cast<uint32_t*>(sg_ln + r * STG_STRIDE + 2 * ln);
                g_gl[(size_t)node * 32 + ln] = v;
            }
        }

        t = tn;
        buf ^= 1;
    }
}

// ---------------------------------------------------------------------------
// 4. Gather-aggregate + fused node update.
//    x[v] = relu( lin[v] + sum_c sigmoid(2*(gt[v]+gb[c])) * linh[c] )
//    Self term lin[v] from own g_gl lane (fp16).
// ---------------------------------------------------------------------------
__global__ void __launch_bounds__(256) gather_kernel() {
    int w = (blockIdx.x * 256 + threadIdx.x) >> 5;
    int l = threadIdx.x & 31;
    if (w >= N_ATOMS) return;

    int beg = __ldg(&g_off[w]);
    int end = __ldg(&g_off[w + 1]);

    __half2 gt = reinterpret_cast<const __half2*>(g_gtop)[(size_t)w * 32 + l];
    uint2 self = __ldg(&g_gl[(size_t)w * 32 + l]);
    float2 acc = __half22float2(*reinterpret_cast<__half2*>(&self.y));

    for (int base = beg; base < end; base += 32) {
        int myc = (base + l < end) ? g_scol[base + l] : 0;
        int m = min(32, end - base);
        #pragma unroll 4
        for (int j = 0; j < m; j++) {
            int cc = __shfl_sync(0xffffffffu, myc, j);
            uint2 v = __ldg(&g_gl[(size_t)cc * 32 + l]);
            __half2 gb = *reinterpret_cast<__half2*>(&v.x);
            __half2 lh = *reinterpret_cast<__half2*>(&v.y);
            __half2 pre = __hadd2(gt, gb);
            uint32_t th_u;
            asm("tanh.approx.f16x2 %0, %1;"
                : "=r"(th_u) : "r"(*reinterpret_cast<uint32_t*>(&pre)));
            __half2 th = *reinterpret_cast<__half2*>(&th_u);
            float2 tf = __half22float2(th);
            float2 lf = __half22float2(lh);
            acc.x += (0.5f * tf.x + 0.5f) * lf.x;
            acc.y += (0.5f * tf.y + 0.5f) * lf.y;
        }
    }

    __half2* xo = reinterpret_cast<__half2*>(g_xh);
    xo[(size_t)w * 32 + l] = __floats2half2_rn(fmaxf(acc.x, 0.0f), fmaxf(acc.y, 0.0f));
}

// ---------------------------------------------------------------------------
// 5. Mean pool
// ---------------------------------------------------------------------------
__global__ void __launch_bounds__(256) pool_kernel() {
    int t = threadIdx.x;
    int col = t & 63;
    int grp = t >> 6;
    float acc = 0.0f;
    for (int node = blockIdx.x * 4 + grp; node < N_ATOMS; node += gridDim.x * 4)
        acc += __half2float(g_xh[(size_t)node * HID + col]);
    __shared__ float s[256];
    s[t] = acc;
    __syncthreads();
    if (grp == 0)
        atomicAdd(&g_pooled[col], s[col] + s[col + 64] + s[col + 128] + s[col + 192]);
}

// ---------------------------------------------------------------------------
// 6. MLP head
// ---------------------------------------------------------------------------
__global__ void head_kernel(const float* __restrict__ W1, const float* __restrict__ b1,
                            const float* __restrict__ W2, const float* __restrict__ b2,
                            float* __restrict__ out) {
    __shared__ float sp[64], sh[64];
    int t = threadIdx.x;
    if (t < 64) sp[t] = g_pooled[t] * (1.0f / (float)N_ATOMS);
    __syncthreads();
    if (t < 64) {
        float a = b1[t];
        #pragma unroll
        for (int k = 0; k < 64; k++) a += sp[k] * W1[k * 64 + t];
        sh[t] = fmaxf(a, 0.0f);
    }
    __syncthreads();
    if (t < 128) {
        float a = b2[t];
        #pragma unroll
        for (int k = 0; k < 64; k++) a += sh[k] * W2[k * 128 + t];
        out[t] = a;
    }
}

// ---------------------------------------------------------------------------
extern "C" void kernel_launch(void* const* d_in, const int* in_sizes, int n_in,
                              void* d_out, int out_size) {
    const int*   an  = (const int*)d_in[0];
    const int*   ei  = (const int*)d_in[3];
    const float* emb = (const float*)d_in[4];
    const float* Wl  = (const float*)d_in[5];
    const float* bl  = (const float*)d_in[6];
    const float* Wg  = (const float*)d_in[7];
    const float* bg  = (const float*)d_in[8];
    const float* W1  = (const float*)d_in[9];
    const float* b1  = (const float*)d_in[10];
    const float* W2  = (const float*)d_in[11];
    const float* b2  = (const float*)d_in[12];
    float* out = (float*)d_out;

    cudaFuncSetAttribute(proj_kernel, cudaFuncAttributeMaxDynamicSharedMemorySize, PROJ_SMEM);

    const int nodeElemBlocks = (N_ATOMS * HID + 255) / 256;   // 25000
    const int edgeBlocks = (N_EDGES + 255) / 256;             // 3907
    const int gatherBlocks = (N_ATOMS * 32 + 255) / 256;      // 12500

    wconv_kernel<<<400, 256>>>(Wg, Wl);                                    // 0 (zeros g_cnt)
    embed_kernel<<<nodeElemBlocks, 256>>>(an, emb, ei);                    // 1 (+hist)
    scan_a_kernel<<<SCAN_NB, SCAN_T>>>();                                  // 2
    proj_kernel<<<PROJ_GRID, 512, PROJ_SMEM>>>(0, bg, bl);                 // 3 <- profiled
    scan_b_kernel<<<1, 256>>>();                                           // 4
    scan_c_kernel<<<SCAN_NB, SCAN_T>>>();                                  // 5
    scatter_kernel<<<edgeBlocks, 256>>>(ei);                               // 6
    gather_kernel<<<gatherBlocks, 256>>>();                                // 7

    for (int l = 1; l < 3; l++) {
        proj_kernel<<<PROJ_GRID, 512, PROJ_SMEM>>>(l, bg + l * 64, bl + l * 64);
        gather_kernel<<<gatherBlocks, 256>>>();
    }
    pool_kernel<<<512, 256>>>();
    head_kernel<<<1, 128>>>(W1, b1, W2, b2, out);
}